// round 2
// baseline (speedup 1.0000x reference)
#include <cuda_runtime.h>
#include <math.h>

// Bidirectional 2-layer LSTM encoder.
// Sizes fixed by the problem:
#define Tn 128
#define Bn 64
#define En 512
#define Hn 1024
#define Gn 4096   // 4*H

// ---------------- scratch (static __device__, no runtime allocs) ----------------
__device__ float g_X [Tn * Bn * En];            // [t][b][e]  embedded input, 16 MB
__device__ float g_Z [2][Tn * Bn * Gn];         // [dir][t][b][4H] input proj + bias, 268 MB (reused layer0->layer1)
__device__ float g_H0[2][Tn * Bn * Hn];         // [dir][t][b][H]  layer-0 outputs, 67 MB
__device__ float g_h [2][2][Bn * Hn];           // [buf][dir] recurrent h (double buffered)
__device__ float g_c [2][Bn * Hn];              // [dir]      cell state (in-place, block-owned columns)

// ---------------- embedding gather ----------------
__global__ void embed_kernel(const int* __restrict__ tokens,
                             const float* __restrict__ emb)
{
    int row = blockIdx.x;            // row = t*Bn + b
    int t = row >> 6;                // /Bn
    int b = row & 63;
    int tok = tokens[b * Tn + t];    // tokens is [B,T]
    const float4* src = (const float4*)(emb + (size_t)tok * En);
    float4*       dst = (float4*)(g_X + (size_t)row * En);
    for (int i = threadIdx.x; i < En / 4; i += blockDim.x) dst[i] = src[i];
}

// ---------------- zero recurrent state ----------------
__global__ void zero_state()
{
    int i = blockIdx.x * blockDim.x + threadIdx.x;
    if (i < Bn * Hn) {
        g_h[0][0][i] = 0.f; g_h[0][1][i] = 0.f;
        g_h[1][0][i] = 0.f; g_h[1][1][i] = 0.f;
        g_c[0][i]    = 0.f; g_c[1][i]    = 0.f;
    }
}

// ---------------- big input-projection GEMM: Z = A @ W + bias ----------------
// A = g_X (K=512, layer 0) or g_H0[dir] (K=1024, layer 1);  W row-major [K][4H].
// Output g_Z[dir][m][col],  M = T*B = 8192, N = 4096.
// grid: (M/64, N/64, 2)  block: 256.  64x64 tile, 4x4 per thread, BK=16.
__global__ __launch_bounds__(256) void gemm_bias(
    int layer,
    const float* __restrict__ W0, const float* __restrict__ W1,
    const float* __restrict__ bb0, const float* __restrict__ bb1)
{
    const int z = blockIdx.z;
    const float* __restrict__ W    = z ? W1  : W0;
    const float* __restrict__ bias = z ? bb1 : bb0;
    const float* __restrict__ A    = layer ? g_H0[z] : g_X;
    const int K = layer ? Hn : En;
    float* __restrict__ C = g_Z[z];

    const int m0 = blockIdx.x * 64;
    const int n0 = blockIdx.y * 64;

    __shared__ float As[16][64];
    __shared__ float Ws[16][64];

    const int tid = threadIdx.x;
    const int tx = tid & 15;          // 0..15 -> 4 output cols
    const int ty = tid >> 4;          // 0..15 -> 4 output rows

    const int arow = tid >> 2;            // 0..63
    const int akq  = (tid & 3) * 4;       // 0,4,8,12
    const int wk   = tid >> 4;            // 0..15
    const int wnq  = (tid & 15) * 4;      // 0..60

    float acc[4][4];
#pragma unroll
    for (int i = 0; i < 4; i++)
#pragma unroll
        for (int j = 0; j < 4; j++) acc[i][j] = 0.f;

    for (int k0 = 0; k0 < K; k0 += 16) {
        float4 av = *(const float4*)(A + (size_t)(m0 + arow) * K + k0 + akq);
        As[akq + 0][arow] = av.x;
        As[akq + 1][arow] = av.y;
        As[akq + 2][arow] = av.z;
        As[akq + 3][arow] = av.w;
        *(float4*)&Ws[wk][wnq] =
            *(const float4*)(W + (size_t)(k0 + wk) * Gn + n0 + wnq);
        __syncthreads();
#pragma unroll
        for (int k = 0; k < 16; k++) {
            float4 a4 = *(float4*)&As[k][ty * 4];
            float4 w4 = *(float4*)&Ws[k][tx * 4];
            float a[4] = {a4.x, a4.y, a4.z, a4.w};
            float w[4] = {w4.x, w4.y, w4.z, w4.w};
#pragma unroll
            for (int i = 0; i < 4; i++)
#pragma unroll
                for (int j = 0; j < 4; j++) acc[i][j] += a[i] * w[j];
        }
        __syncthreads();
    }

#pragma unroll
    for (int i = 0; i < 4; i++) {
        int row = m0 + ty * 4 + i;
#pragma unroll
        for (int j = 0; j < 4; j++) {
            int col = n0 + tx * 4 + j;
            C[(size_t)row * Gn + col] = acc[i][j] + bias[col];
        }
    }
}

// ---------------- recurrent step (fused h@U GEMM + gates + state update) ----------------
// For scan step t, both directions (blockIdx.z = dir). Block owns h-columns
// [n0, n0+16) and computes all 4 gates for those columns over all 64 batch rows.
// grid: (H/16 = 64, 1, 2), block 256 = (16 cols) x (16 row-groups of 4).
__global__ __launch_bounds__(256) void lstm_step(
    int layer, int t,
    const float* __restrict__ Ud0, const float* __restrict__ Ud1,
    float* __restrict__ out)
{
    const int z = blockIdx.z;
    const int t_eff = z ? (Tn - 1 - t) : t;
    const float* __restrict__ U = z ? Ud1 : Ud0;
    const int buf = t & 1;
    const float* __restrict__ hprev = g_h[buf][z];
    float* __restrict__ hnew = g_h[buf ^ 1][z];
    float* __restrict__ cst = g_c[z];
    const float* __restrict__ Zrow = g_Z[z] + (size_t)t_eff * Bn * Gn;
    const int n0 = blockIdx.x * 16;

    __shared__ float Hs[16][64];       // [k][b]
    __shared__ float Us[16][4][16];    // [k][gate][col]

    const int tid = threadIdx.x;
    const int tx = tid & 15;           // col within tile
    const int ty = tid >> 4;           // row group (4 rows each)

    const int hb  = tid >> 2;          // 0..63 batch row for H load
    const int hkq = (tid & 3) * 4;     // 0,4,8,12
    const int uk  = tid >> 4;          // 0..15
    const int ug  = (tid >> 2) & 3;    // gate
    const int uq  = (tid & 3) * 4;     // col quad

    float acc[4][4];                   // [gate][row]
#pragma unroll
    for (int g = 0; g < 4; g++)
#pragma unroll
        for (int r = 0; r < 4; r++) acc[g][r] = 0.f;

    for (int k0 = 0; k0 < Hn; k0 += 16) {
        float4 hv = *(const float4*)(hprev + hb * Hn + k0 + hkq);
        Hs[hkq + 0][hb] = hv.x;
        Hs[hkq + 1][hb] = hv.y;
        Hs[hkq + 2][hb] = hv.z;
        Hs[hkq + 3][hb] = hv.w;
        *(float4*)&Us[uk][ug][uq] =
            *(const float4*)(U + (size_t)(k0 + uk) * Gn + ug * Hn + n0 + uq);
        __syncthreads();
#pragma unroll
        for (int k = 0; k < 16; k++) {
            float4 h4 = *(float4*)&Hs[k][ty * 4];
            float hr[4] = {h4.x, h4.y, h4.z, h4.w};
            float u[4];
#pragma unroll
            for (int g = 0; g < 4; g++) u[g] = Us[k][g][tx];
#pragma unroll
            for (int g = 0; g < 4; g++)
#pragma unroll
                for (int r = 0; r < 4; r++) acc[g][r] += hr[r] * u[g];
        }
        __syncthreads();
    }

    const int n = n0 + tx;
#pragma unroll
    for (int r = 0; r < 4; r++) {
        const int b = ty * 4 + r;
        const float* zb = Zrow + (size_t)b * Gn;
        float zi = acc[0][r] + zb[n];
        float zf = acc[1][r] + zb[Hn + n];
        float zg = acc[2][r] + zb[2 * Hn + n];
        float zo = acc[3][r] + zb[3 * Hn + n];

        float ig = 1.f / (1.f + __expf(-zi));
        float fg = 1.f / (1.f + __expf(-zf));
        float gg = tanhf(zg);
        float og = 1.f / (1.f + __expf(-zo));

        float cn = fg * cst[b * Hn + n] + ig * gg;
        cst[b * Hn + n] = cn;
        float hv = og * tanhf(cn);
        hnew[b * Hn + n] = hv;

        if (layer == 0) {
            g_H0[z][(size_t)t_eff * Bn * Hn + (size_t)b * Hn + n] = hv;
        } else {
            // output[b][t_eff][dir*H + n]
            out[(size_t)b * Tn * 2 * Hn + (size_t)t_eff * 2 * Hn + (size_t)z * Hn + n] = hv;
        }
        // forward-direction final states (t == T-1) go to the tail of d_out:
        // [output | h_f0 | c_f0 | h_f1 | c_f1]
        if (z == 0 && t == Tn - 1) {
            size_t base = (size_t)Bn * Tn * 2 * Hn + (size_t)layer * 2 * Bn * Hn;
            out[base + (size_t)b * Hn + n] = hv;
            out[base + (size_t)Bn * Hn + (size_t)b * Hn + n] = cn;
        }
    }
}

// ---------------- launch ----------------
extern "C" void kernel_launch(void* const* d_in, const int* in_sizes, int n_in,
                              void* d_out, int out_size)
{
    (void)in_sizes; (void)n_in; (void)out_size;
    const int*   tokens = (const int*)  d_in[0];
    const float* emb    = (const float*)d_in[1];
    const float* W_f0   = (const float*)d_in[2];
    const float* U_f0   = (const float*)d_in[3];
    const float* b_f0   = (const float*)d_in[4];
    const float* W_f1   = (const float*)d_in[5];
    const float* U_f1   = (const float*)d_in[6];
    const float* b_f1   = (const float*)d_in[7];
    const float* W_b0   = (const float*)d_in[8];
    const float* U_b0   = (const float*)d_in[9];
    const float* b_b0   = (const float*)d_in[10];
    const float* W_b1   = (const float*)d_in[11];
    const float* U_b1   = (const float*)d_in[12];
    const float* b_b1   = (const float*)d_in[13];
    float* out = (float*)d_out;

    // 1) embedding gather -> g_X
    embed_kernel<<<Tn * Bn, 128>>>(tokens, emb);

    // 2) layer-0 input projections (both dirs), K = E = 512
    gemm_bias<<<dim3(Tn * Bn / 64, Gn / 64, 2), 256>>>(0, W_f0, W_b0, b_f0, b_b0);

    // 3) layer-0 recurrence (fwd + bwd concurrently)
    zero_state<<<(Bn * Hn + 255) / 256, 256>>>();
    for (int t = 0; t < Tn; t++)
        lstm_step<<<dim3(Hn / 16, 1, 2), 256>>>(0, t, U_f0, U_b0, out);

    // 4) layer-1 input projections from g_H0 (both dirs), K = H = 1024 (reuses g_Z)
    gemm_bias<<<dim3(Tn * Bn / 64, Gn / 64, 2), 256>>>(1, W_f1, W_b1, b_f1, b_b1);

    // 5) layer-1 recurrence, writes directly into d_out
    zero_state<<<(Bn * Hn + 255) / 256, 256>>>();
    for (int t = 0; t < Tn; t++)
        lstm_step<<<dim3(Hn / 16, 1, 2), 256>>>(1, t, U_f1, U_b1, out);
}

// round 4
// speedup vs baseline: 1.5561x; 1.5561x over previous
#include <cuda_runtime.h>
#include <cuda_bf16.h>
#include <math.h>

// Bidirectional 2-layer LSTM encoder — split-bf16 tensor-core version.
// B=64, T=128, E=512, H=1024.  Gate order (Keras): i, f, g, o.
// Gate-interleaved column space: n' = h*4 + g  (h in [0,1024), g in [0,4)).

#define Tn 128
#define Bn 64
#define En 512
#define Hn 1024
#define Gn 4096          // 4*H
#define Mrows (Tn*Bn)    // 8192

typedef unsigned short ushort_t;

// ---------------- static device scratch ----------------
__device__ ushort_t g_X_hi [Mrows * En];
__device__ ushort_t g_X_lo [Mrows * En];
__device__ float    g_Z    [2][Mrows * Gn];          // [dir][t*B+b][n']  fp32, bias folded
__device__ ushort_t g_H0_hi[2][Mrows * Hn];          // layer-0 outputs (bf16 hi/lo)
__device__ ushort_t g_H0_lo[2][Mrows * Hn];
__device__ ushort_t g_hh_hi[2][2][Bn * Hn];          // [buf][dir] recurrent h
__device__ ushort_t g_hh_lo[2][2][Bn * Hn];
__device__ float    g_c    [2][Bn * Hn];             // [dir] cell state

// transposed + gate-interleaved weights, bf16 hi/lo: [n'][K]
__device__ ushort_t g_Wt0_hi[2][Gn * En];   // layer 0 input weights, K=512
__device__ ushort_t g_Wt0_lo[2][Gn * En];
__device__ ushort_t g_Wt1_hi[2][Gn * Hn];   // layer 1 input weights, K=1024
__device__ ushort_t g_Wt1_lo[2][Gn * Hn];
__device__ ushort_t g_Ut_hi [2][2][Gn * Hn]; // [layer][dir] recurrent weights
__device__ ushort_t g_Ut_lo [2][2][Gn * Hn];

// ---------------- helpers ----------------
__device__ __forceinline__ void split_bf16(float v, ushort_t& hi, ushort_t& lo)
{
    __nv_bfloat16 h = __float2bfloat16(v);
    float r = v - __bfloat162float(h);
    __nv_bfloat16 l = __float2bfloat16(r);
    hi = *reinterpret_cast<ushort_t*>(&h);
    lo = *reinterpret_cast<ushort_t*>(&l);
}

__device__ __forceinline__ void mma16816(float* c, const unsigned* a, const unsigned* b)
{
    asm volatile(
        "mma.sync.aligned.m16n8k16.row.col.f32.bf16.bf16.f32 "
        "{%0,%1,%2,%3}, {%4,%5,%6,%7}, {%8,%9}, {%0,%1,%2,%3};\n"
        : "+f"(c[0]), "+f"(c[1]), "+f"(c[2]), "+f"(c[3])
        : "r"(a[0]), "r"(a[1]), "r"(a[2]), "r"(a[3]), "r"(b[0]), "r"(b[1]));
}

// A fragment (m16k16, row-major, rows r0..r0+15, k cols kk..kk+15)
__device__ __forceinline__ void load_a_frag(unsigned* a, const ushort_t (*As)[40],
                                            int r0, int kk, int lane)
{
    int r = r0 + (lane >> 2);
    int k = kk + (lane & 3) * 2;
    a[0] = *(const unsigned*)&As[r][k];
    a[1] = *(const unsigned*)&As[r + 8][k];
    a[2] = *(const unsigned*)&As[r][k + 8];
    a[3] = *(const unsigned*)&As[r + 8][k + 8];
}

// B fragment (k16n8, col-major == Bs stored [n][k] k-contiguous)
__device__ __forceinline__ void load_b_frag(unsigned* b, const ushort_t (*Bs)[40],
                                            int nb, int kk, int lane)
{
    int n = nb + (lane >> 2);
    int k = kk + (lane & 3) * 2;
    b[0] = *(const unsigned*)&Bs[n][k];
    b[1] = *(const unsigned*)&Bs[n][k + 8];
}

__device__ __forceinline__ float sigmoidf_(float x) { return 1.f / (1.f + __expf(-x)); }

// ---------------- weight conversion: fp32 [K][4096] -> bf16 hi/lo [n'][K] ----------------
// grid: (K/32, 4096/32), block (32,8)
__global__ void conv_wt(const float* __restrict__ src,
                        ushort_t* __restrict__ dhi, ushort_t* __restrict__ dlo, int K)
{
    __shared__ float tile[32][33];
    int k0 = blockIdx.x * 32;
    int n0 = blockIdx.y * 32;
    int tx = threadIdx.x, ty = threadIdx.y;
#pragma unroll
    for (int j = 0; j < 4; j++)
        tile[ty + j * 8][tx] = src[(size_t)(k0 + ty + j * 8) * Gn + n0 + tx];
    __syncthreads();
#pragma unroll
    for (int j = 0; j < 4; j++) {
        int b = ty + j * 8;
        int n = n0 + b;
        int np = ((n & 1023) << 2) | (n >> 10);   // n' = h*4 + g
        float v = tile[tx][b];
        ushort_t hi, lo; split_bf16(v, hi, lo);
        dhi[(size_t)np * K + k0 + tx] = hi;
        dlo[(size_t)np * K + k0 + tx] = lo;
    }
}

// ---------------- embedding gather + split ----------------
__global__ void embed_split(const int* __restrict__ tokens, const float* __restrict__ emb)
{
    int row = blockIdx.x;          // t*Bn + b
    int t = row >> 6, b = row & 63;
    int tok = tokens[b * Tn + t];
    const float4* src = (const float4*)(emb + (size_t)tok * En);
    for (int i = threadIdx.x; i < En / 4; i += blockDim.x) {
        float4 v = src[i];
        ushort_t h0,l0,h1,l1,h2,l2,h3,l3;
        split_bf16(v.x,h0,l0); split_bf16(v.y,h1,l1);
        split_bf16(v.z,h2,l2); split_bf16(v.w,h3,l3);
        size_t o = (size_t)row * En + i * 4;
        g_X_hi[o]=h0; g_X_hi[o+1]=h1; g_X_hi[o+2]=h2; g_X_hi[o+3]=h3;
        g_X_lo[o]=l0; g_X_lo[o+1]=l1; g_X_lo[o+2]=l2; g_X_lo[o+3]=l3;
    }
}

// ---------------- zero recurrent state ----------------
__global__ void zero_state()
{
    int i = blockIdx.x * blockDim.x + threadIdx.x;
    if (i < Bn * Hn) {
        g_hh_hi[0][0][i]=0; g_hh_hi[0][1][i]=0; g_hh_hi[1][0][i]=0; g_hh_hi[1][1][i]=0;
        g_hh_lo[0][0][i]=0; g_hh_lo[0][1][i]=0; g_hh_lo[1][0][i]=0; g_hh_lo[1][1][i]=0;
        g_c[0][i]=0.f; g_c[1][i]=0.f;
    }
}

// ---------------- input projection GEMM (split-bf16 mma): Z = A @ Wt^T + bias ----------------
// A: [8192][K] bf16 hi/lo.  Wt: [4096 n'][K].  C: g_Z[z] fp32 [8192][4096 n'].
// grid (128, 64, 2), block 128 (4 warps, 2x2 of 32x32 tiles). BK=32.
__global__ __launch_bounds__(128) void gemm_mma(int layer,
                                                const float* __restrict__ bb0,
                                                const float* __restrict__ bb1)
{
    const int z = blockIdx.z;
    const int K = layer ? Hn : En;
    const ushort_t* __restrict__ Ah = layer ? g_H0_hi[z] : g_X_hi;
    const ushort_t* __restrict__ Al = layer ? g_H0_lo[z] : g_X_lo;
    const ushort_t* __restrict__ Bh = layer ? g_Wt1_hi[z] : g_Wt0_hi[z];
    const ushort_t* __restrict__ Bl = layer ? g_Wt1_lo[z] : g_Wt0_lo[z];
    const float* __restrict__ bias = z ? bb1 : bb0;
    float* __restrict__ C = g_Z[z];

    const int m0 = blockIdx.x * 64;
    const int n0 = blockIdx.y * 64;

    __shared__ ushort_t As_h[64][40], As_l[64][40], Bs_h[64][40], Bs_l[64][40];

    const int t = threadIdx.x;
    const int lane = t & 31, warp = t >> 5;
    const int wm = warp >> 1, wn = warp & 1;
    const int lr = t >> 2;           // 0..31
    const int lk = (t & 3) * 8;      // 0,8,16,24

    float acc[2][4][4];
#pragma unroll
    for (int mt = 0; mt < 2; mt++)
#pragma unroll
        for (int nt = 0; nt < 4; nt++)
#pragma unroll
            for (int i = 0; i < 4; i++) acc[mt][nt][i] = 0.f;

    for (int k0 = 0; k0 < K; k0 += 32) {
#pragma unroll
        for (int half = 0; half < 2; half++) {
            int r = lr + half * 32;
            *(uint4*)&As_h[r][lk] = *(const uint4*)(Ah + (size_t)(m0 + r) * K + k0 + lk);
            *(uint4*)&As_l[r][lk] = *(const uint4*)(Al + (size_t)(m0 + r) * K + k0 + lk);
            *(uint4*)&Bs_h[r][lk] = *(const uint4*)(Bh + (size_t)(n0 + r) * K + k0 + lk);
            *(uint4*)&Bs_l[r][lk] = *(const uint4*)(Bl + (size_t)(n0 + r) * K + k0 + lk);
        }
        __syncthreads();
#pragma unroll
        for (int kk = 0; kk < 32; kk += 16) {
            unsigned ah[2][4], al[2][4], bh[4][2], bl[4][2];
#pragma unroll
            for (int mt = 0; mt < 2; mt++) {
                load_a_frag(ah[mt], As_h, wm * 32 + mt * 16, kk, lane);
                load_a_frag(al[mt], As_l, wm * 32 + mt * 16, kk, lane);
            }
#pragma unroll
            for (int nt = 0; nt < 4; nt++) {
                load_b_frag(bh[nt], Bs_h, wn * 32 + nt * 8, kk, lane);
                load_b_frag(bl[nt], Bs_l, wn * 32 + nt * 8, kk, lane);
            }
#pragma unroll
            for (int mt = 0; mt < 2; mt++)
#pragma unroll
                for (int nt = 0; nt < 4; nt++) {
                    mma16816(acc[mt][nt], ah[mt], bh[nt]);
                    mma16816(acc[mt][nt], ah[mt], bl[nt]);
                    mma16816(acc[mt][nt], al[mt], bh[nt]);
                }
        }
        __syncthreads();
    }

#pragma unroll
    for (int mt = 0; mt < 2; mt++)
#pragma unroll
        for (int nt = 0; nt < 4; nt++) {
            int r  = m0 + wm * 32 + mt * 16 + (lane >> 2);
            int cg = n0 + wn * 32 + nt * 8 + (lane & 3) * 2;
            float b0 = bias[((cg & 3) << 10) | (cg >> 2)];
            float b1 = bias[(((cg + 1) & 3) << 10) | ((cg + 1) >> 2)];
            C[(size_t)r * Gn + cg]           = acc[mt][nt][0] + b0;
            C[(size_t)r * Gn + cg + 1]       = acc[mt][nt][1] + b1;
            C[(size_t)(r + 8) * Gn + cg]     = acc[mt][nt][2] + b0;
            C[(size_t)(r + 8) * Gn + cg + 1] = acc[mt][nt][3] + b1;
        }
}

// ---------------- recurrent step: h@U (split-bf16 mma) + gates + state update ----------------
// grid (64, 1, 2): block owns n' columns [n0, n0+64) = 16 hidden units x 4 gates.
__global__ __launch_bounds__(128) void lstm_step_mma(int layer, int tstep,
                                                     float* __restrict__ out)
{
    const int z = blockIdx.z;
    const int t_eff = z ? (Tn - 1 - tstep) : tstep;
    const int buf = tstep & 1;
    const ushort_t* __restrict__ Ah = g_hh_hi[buf][z];
    const ushort_t* __restrict__ Al = g_hh_lo[buf][z];
    const ushort_t* __restrict__ Bh = g_Ut_hi[layer][z];
    const ushort_t* __restrict__ Bl = g_Ut_lo[layer][z];
    ushort_t* __restrict__ Hnh = g_hh_hi[buf ^ 1][z];
    ushort_t* __restrict__ Hnl = g_hh_lo[buf ^ 1][z];
    float* __restrict__ cst = g_c[z];
    const float* __restrict__ Zrow = g_Z[z] + (size_t)t_eff * Bn * Gn;
    const int n0 = blockIdx.x * 64;

    __shared__ ushort_t As_h[64][40], As_l[64][40], Bs_h[64][40], Bs_l[64][40];

    const int t = threadIdx.x;
    const int lane = t & 31, warp = t >> 5;
    const int wm = warp >> 1, wn = warp & 1;
    const int lr = t >> 2;
    const int lk = (t & 3) * 8;

    float acc[2][4][4];
#pragma unroll
    for (int mt = 0; mt < 2; mt++)
#pragma unroll
        for (int nt = 0; nt < 4; nt++)
#pragma unroll
            for (int i = 0; i < 4; i++) acc[mt][nt][i] = 0.f;

    for (int k0 = 0; k0 < Hn; k0 += 32) {
#pragma unroll
        for (int half = 0; half < 2; half++) {
            int r = lr + half * 32;
            *(uint4*)&As_h[r][lk] = *(const uint4*)(Ah + (size_t)r * Hn + k0 + lk);
            *(uint4*)&As_l[r][lk] = *(const uint4*)(Al + (size_t)r * Hn + k0 + lk);
            *(uint4*)&Bs_h[r][lk] = *(const uint4*)(Bh + (size_t)(n0 + r) * Hn + k0 + lk);
            *(uint4*)&Bs_l[r][lk] = *(const uint4*)(Bl + (size_t)(n0 + r) * Hn + k0 + lk);
        }
        __syncthreads();
#pragma unroll
        for (int kk = 0; kk < 32; kk += 16) {
            unsigned ah[2][4], al[2][4], bh[4][2], bl[4][2];
#pragma unroll
            for (int mt = 0; mt < 2; mt++) {
                load_a_frag(ah[mt], As_h, wm * 32 + mt * 16, kk, lane);
                load_a_frag(al[mt], As_l, wm * 32 + mt * 16, kk, lane);
            }
#pragma unroll
            for (int nt = 0; nt < 4; nt++) {
                load_b_frag(bh[nt], Bs_h, wn * 32 + nt * 8, kk, lane);
                load_b_frag(bl[nt], Bs_l, wn * 32 + nt * 8, kk, lane);
            }
#pragma unroll
            for (int mt = 0; mt < 2; mt++)
#pragma unroll
                for (int nt = 0; nt < 4; nt++) {
                    mma16816(acc[mt][nt], ah[mt], bh[nt]);
                    mma16816(acc[mt][nt], ah[mt], bl[nt]);
                    mma16816(acc[mt][nt], al[mt], bh[nt]);
                }
        }
        __syncthreads();
    }

    // epilogue: lane pairs (even: gates i,f | odd: gates g,o of same hidden unit)
#pragma unroll
    for (int mt = 0; mt < 2; mt++)
#pragma unroll
        for (int nt = 0; nt < 4; nt++) {
            float p0 = __shfl_xor_sync(0xffffffffu, acc[mt][nt][0], 1);
            float p1 = __shfl_xor_sync(0xffffffffu, acc[mt][nt][1], 1);
            float p2 = __shfl_xor_sync(0xffffffffu, acc[mt][nt][2], 1);
            float p3 = __shfl_xor_sync(0xffffffffu, acc[mt][nt][3], 1);
            if ((lane & 1) == 0) {
                int b0r = wm * 32 + mt * 16 + (lane >> 2);      // batch row (and +8)
                int cg  = n0 + wn * 32 + nt * 8 + (lane & 3) * 2;  // n' (multiple of 4)
                int h   = cg >> 2;
#pragma unroll
                for (int rr = 0; rr < 2; rr++) {
                    int b = b0r + rr * 8;
                    float ui = rr ? acc[mt][nt][2] : acc[mt][nt][0];
                    float uf = rr ? acc[mt][nt][3] : acc[mt][nt][1];
                    float ug = rr ? p2 : p0;
                    float uo = rr ? p3 : p1;
                    float4 z4 = *(const float4*)(Zrow + (size_t)b * Gn + (h << 2));
                    float ig = sigmoidf_(z4.x + ui);
                    float fg = sigmoidf_(z4.y + uf);
                    float gg = tanhf(z4.z + ug);
                    float og = sigmoidf_(z4.w + uo);
                    float cn = fg * cst[b * Hn + h] + ig * gg;
                    cst[b * Hn + h] = cn;
                    float hv = og * tanhf(cn);
                    ushort_t hh, hl; split_bf16(hv, hh, hl);
                    Hnh[b * Hn + h] = hh;
                    Hnl[b * Hn + h] = hl;
                    if (layer == 0) {
                        size_t o = (size_t)(t_eff * Bn + b) * Hn + h;
                        g_H0_hi[z][o] = hh;
                        g_H0_lo[z][o] = hl;
                    } else {
                        out[(size_t)b * Tn * 2 * Hn + (size_t)t_eff * 2 * Hn
                            + (size_t)z * Hn + h] = hv;
                    }
                    if (z == 0 && tstep == Tn - 1) {
                        size_t base = (size_t)Bn * Tn * 2 * Hn
                                    + (size_t)layer * 2 * Bn * Hn;
                        out[base + (size_t)b * Hn + h] = hv;
                        out[base + (size_t)Bn * Hn + (size_t)b * Hn + h] = cn;
                    }
                }
            }
        }
}

// ---------------- launch ----------------
extern "C" void kernel_launch(void* const* d_in, const int* in_sizes, int n_in,
                              void* d_out, int out_size)
{
    (void)in_sizes; (void)n_in; (void)out_size;
    const int*   tokens = (const int*)  d_in[0];
    const float* emb    = (const float*)d_in[1];
    const float* W_f0   = (const float*)d_in[2];
    const float* U_f0   = (const float*)d_in[3];
    const float* b_f0   = (const float*)d_in[4];
    const float* W_f1   = (const float*)d_in[5];
    const float* U_f1   = (const float*)d_in[6];
    const float* b_f1   = (const float*)d_in[7];
    const float* W_b0   = (const float*)d_in[8];
    const float* U_b0   = (const float*)d_in[9];
    const float* b_b0   = (const float*)d_in[10];
    const float* W_b1   = (const float*)d_in[11];
    const float* U_b1   = (const float*)d_in[12];
    const float* b_b1   = (const float*)d_in[13];
    float* out = (float*)d_out;

    // resolve device scratch addresses for conversion outputs
    ushort_t *wt0h, *wt0l, *wt1h, *wt1l, *uth, *utl;
    cudaGetSymbolAddress((void**)&wt0h, g_Wt0_hi);
    cudaGetSymbolAddress((void**)&wt0l, g_Wt0_lo);
    cudaGetSymbolAddress((void**)&wt1h, g_Wt1_hi);
    cudaGetSymbolAddress((void**)&wt1l, g_Wt1_lo);
    cudaGetSymbolAddress((void**)&uth,  g_Ut_hi);
    cudaGetSymbolAddress((void**)&utl,  g_Ut_lo);

    dim3 cb(32, 8);
    // layer-0 input weights (K=512): [dir]
    conv_wt<<<dim3(En / 32, Gn / 32), cb>>>(W_f0, wt0h,               wt0l,               En);
    conv_wt<<<dim3(En / 32, Gn / 32), cb>>>(W_b0, wt0h + Gn * En,     wt0l + Gn * En,     En);
    // layer-1 input weights (K=1024)
    conv_wt<<<dim3(Hn / 32, Gn / 32), cb>>>(W_f1, wt1h,               wt1l,               Hn);
    conv_wt<<<dim3(Hn / 32, Gn / 32), cb>>>(W_b1, wt1h + Gn * Hn,     wt1l + Gn * Hn,     Hn);
    // recurrent weights [layer][dir]
    conv_wt<<<dim3(Hn / 32, Gn / 32), cb>>>(U_f0, uth,                 utl,                 Hn);
    conv_wt<<<dim3(Hn / 32, Gn / 32), cb>>>(U_b0, uth + Gn * Hn,       utl + Gn * Hn,       Hn);
    conv_wt<<<dim3(Hn / 32, Gn / 32), cb>>>(U_f1, uth + 2 * Gn * Hn,   utl + 2 * Gn * Hn,   Hn);
    conv_wt<<<dim3(Hn / 32, Gn / 32), cb>>>(U_b1, uth + 3 * Gn * Hn,   utl + 3 * Gn * Hn,   Hn);

    // embedding gather + split
    embed_split<<<Mrows, 128>>>(tokens, emb);

    // layer-0 input projections (both dirs)
    gemm_mma<<<dim3(Mrows / 64, Gn / 64, 2), 128>>>(0, b_f0, b_b0);

    // layer-0 recurrence
    zero_state<<<(Bn * Hn + 255) / 256, 256>>>();
    for (int t = 0; t < Tn; t++)
        lstm_step_mma<<<dim3(Gn / 64, 1, 2), 128>>>(0, t, out);

    // layer-1 input projections from layer-0 outputs
    gemm_mma<<<dim3(Mrows / 64, Gn / 64, 2), 128>>>(1, b_f1, b_b1);

    // layer-1 recurrence (writes d_out)
    zero_state<<<(Bn * Hn + 255) / 256, 256>>>();
    for (int t = 0; t < Tn; t++)
        lstm_step_mma<<<dim3(Gn / 64, 1, 2), 128>>>(1, t, out);
}

// round 6
// speedup vs baseline: 2.4871x; 1.5983x over previous
#include <cuda_runtime.h>
#include <cuda_bf16.h>
#include <math.h>

// Bidirectional 2-layer LSTM encoder — split-bf16 tensor cores + persistent recurrence.
// B=64, T=128, E=512, H=1024.  Gate order (Keras): i, f, g, o.
// Gate-interleaved column space: n' = h*4 + g.

#define Tn 128
#define Bn 64
#define En 512
#define Hn 1024
#define Gn 4096
#define Mrows (Tn*Bn)

typedef unsigned short ushort_t;
typedef unsigned int   uint_t;

// ---------------- static device scratch ----------------
__device__ ushort_t g_X_hi [Mrows * En];
__device__ ushort_t g_X_lo [Mrows * En];
__device__ float    g_Z    [2][Mrows * Gn];          // [dir][row][n'] fp32, bias folded
__device__ ushort_t g_H0_hi[2][Mrows * Hn];
__device__ ushort_t g_H0_lo[2][Mrows * Hn];
__device__ ushort_t g_hh_hi[2][2][Bn * Hn];          // [buf][dir]
__device__ ushort_t g_hh_lo[2][2][Bn * Hn];
__device__ int      g_ctr  [2 * Tn];                 // [dir][t] arrival counters

__device__ ushort_t g_Wt0_hi[2][Gn * En];
__device__ ushort_t g_Wt0_lo[2][Gn * En];
__device__ ushort_t g_Wt1_hi[2][Gn * Hn];
__device__ ushort_t g_Wt1_lo[2][Gn * Hn];
__device__ ushort_t g_Ut_hi [2][2][Gn * Hn];         // [layer][dir], [n'][K]
__device__ ushort_t g_Ut_lo [2][2][Gn * Hn];

// ---------------- helpers ----------------
__device__ __forceinline__ void split_bf16(float v, ushort_t& hi, ushort_t& lo)
{
    __nv_bfloat16 h = __float2bfloat16(v);
    float r = v - __bfloat162float(h);
    __nv_bfloat16 l = __float2bfloat16(r);
    hi = *reinterpret_cast<ushort_t*>(&h);
    lo = *reinterpret_cast<ushort_t*>(&l);
}

__device__ __forceinline__ void mma16816(float* c, const uint_t* a, const uint_t* b)
{
    asm volatile(
        "mma.sync.aligned.m16n8k16.row.col.f32.bf16.bf16.f32 "
        "{%0,%1,%2,%3}, {%4,%5,%6,%7}, {%8,%9}, {%0,%1,%2,%3};\n"
        : "+f"(c[0]), "+f"(c[1]), "+f"(c[2]), "+f"(c[3])
        : "r"(a[0]), "r"(a[1]), "r"(a[2]), "r"(a[3]), "r"(b[0]), "r"(b[1]));
}

__device__ __forceinline__ void ldsm4(uint_t* a, uint_t saddr)
{
    asm volatile("ldmatrix.sync.aligned.m8n8.x4.shared.b16 {%0,%1,%2,%3}, [%4];"
        : "=r"(a[0]), "=r"(a[1]), "=r"(a[2]), "=r"(a[3]) : "r"(saddr));
}
__device__ __forceinline__ void ldsm2(uint_t* b, uint_t saddr)
{
    asm volatile("ldmatrix.sync.aligned.m8n8.x2.shared.b16 {%0,%1}, [%2];"
        : "=r"(b[0]), "=r"(b[1]) : "r"(saddr));
}

__device__ __forceinline__ int ldcg_i(const int* p)
{
    int v; asm volatile("ld.global.cg.b32 %0, [%1];" : "=r"(v) : "l"(p)); return v;
}

__device__ __forceinline__ float sigmoidf_(float x) { return 1.f / (1.f + __expf(-x)); }

// fragment loaders for the projection GEMM (smem stride 40)
__device__ __forceinline__ void load_a_frag(uint_t* a, const ushort_t (*As)[40],
                                            int r0, int kk, int lane)
{
    int r = r0 + (lane >> 2);
    int k = kk + (lane & 3) * 2;
    a[0] = *(const uint_t*)&As[r][k];
    a[1] = *(const uint_t*)&As[r + 8][k];
    a[2] = *(const uint_t*)&As[r][k + 8];
    a[3] = *(const uint_t*)&As[r + 8][k + 8];
}
__device__ __forceinline__ void load_b_frag(uint_t* b, const ushort_t (*Bs)[40],
                                            int nb, int kk, int lane)
{
    int n = nb + (lane >> 2);
    int k = kk + (lane & 3) * 2;
    b[0] = *(const uint_t*)&Bs[n][k];
    b[1] = *(const uint_t*)&Bs[n][k + 8];
}

// ---------------- weight conversion: fp32 [K][4096] -> bf16 hi/lo [n'][K] ----------------
__global__ void conv_wt(const float* __restrict__ src,
                        ushort_t* __restrict__ dhi, ushort_t* __restrict__ dlo, int K)
{
    __shared__ float tile[32][33];
    int k0 = blockIdx.x * 32;
    int n0 = blockIdx.y * 32;
    int tx = threadIdx.x, ty = threadIdx.y;
#pragma unroll
    for (int j = 0; j < 4; j++)
        tile[ty + j * 8][tx] = src[(size_t)(k0 + ty + j * 8) * Gn + n0 + tx];
    __syncthreads();
#pragma unroll
    for (int j = 0; j < 4; j++) {
        int b = ty + j * 8;
        int n = n0 + b;
        int np = ((n & 1023) << 2) | (n >> 10);   // n' = h*4 + g
        float v = tile[tx][b];
        ushort_t hi, lo; split_bf16(v, hi, lo);
        dhi[(size_t)np * K + k0 + tx] = hi;
        dlo[(size_t)np * K + k0 + tx] = lo;
    }
}

// ---------------- embedding gather + split ----------------
__global__ void embed_split(const int* __restrict__ tokens, const float* __restrict__ emb)
{
    int row = blockIdx.x;          // t*Bn + b
    int t = row >> 6, b = row & 63;
    int tok = tokens[b * Tn + t];
    const float4* src = (const float4*)(emb + (size_t)tok * En);
    for (int i = threadIdx.x; i < En / 4; i += blockDim.x) {
        float4 v = src[i];
        ushort_t h0,l0,h1,l1,h2,l2,h3,l3;
        split_bf16(v.x,h0,l0); split_bf16(v.y,h1,l1);
        split_bf16(v.z,h2,l2); split_bf16(v.w,h3,l3);
        size_t o = (size_t)row * En + i * 4;
        g_X_hi[o]=h0; g_X_hi[o+1]=h1; g_X_hi[o+2]=h2; g_X_hi[o+3]=h3;
        g_X_lo[o]=l0; g_X_lo[o+1]=l1; g_X_lo[o+2]=l2; g_X_lo[o+3]=l3;
    }
}

// ---------------- zero recurrent state + counters ----------------
__global__ void zero_state()
{
    int i = blockIdx.x * blockDim.x + threadIdx.x;
    if (i < Bn * Hn) {
        g_hh_hi[0][0][i]=0; g_hh_hi[0][1][i]=0; g_hh_hi[1][0][i]=0; g_hh_hi[1][1][i]=0;
        g_hh_lo[0][0][i]=0; g_hh_lo[0][1][i]=0; g_hh_lo[1][0][i]=0; g_hh_lo[1][1][i]=0;
    }
    if (blockIdx.x == 0 && threadIdx.x < 2 * Tn) g_ctr[threadIdx.x] = 0;
}

// ---------------- input projection GEMM (split-bf16 mma): Z = A @ Wt^T + bias ----------------
__global__ __launch_bounds__(128) void gemm_mma(int layer,
                                                const float* __restrict__ bb0,
                                                const float* __restrict__ bb1)
{
    const int z = blockIdx.z;
    const int K = layer ? Hn : En;
    const ushort_t* __restrict__ Ah = layer ? g_H0_hi[z] : g_X_hi;
    const ushort_t* __restrict__ Al = layer ? g_H0_lo[z] : g_X_lo;
    const ushort_t* __restrict__ Bh = layer ? g_Wt1_hi[z] : g_Wt0_hi[z];
    const ushort_t* __restrict__ Bl = layer ? g_Wt1_lo[z] : g_Wt0_lo[z];
    const float* __restrict__ bias = z ? bb1 : bb0;
    float* __restrict__ C = g_Z[z];

    const int m0 = blockIdx.x * 64;
    const int n0 = blockIdx.y * 64;

    __shared__ ushort_t As_h[64][40], As_l[64][40], Bs_h[64][40], Bs_l[64][40];

    const int t = threadIdx.x;
    const int lane = t & 31, warp = t >> 5;
    const int wm = warp >> 1, wn = warp & 1;
    const int lr = t >> 2;
    const int lk = (t & 3) * 8;

    float acc[2][4][4];
#pragma unroll
    for (int mt = 0; mt < 2; mt++)
#pragma unroll
        for (int nt = 0; nt < 4; nt++)
#pragma unroll
            for (int i = 0; i < 4; i++) acc[mt][nt][i] = 0.f;

    for (int k0 = 0; k0 < K; k0 += 32) {
#pragma unroll
        for (int half = 0; half < 2; half++) {
            int r = lr + half * 32;
            *(uint4*)&As_h[r][lk] = *(const uint4*)(Ah + (size_t)(m0 + r) * K + k0 + lk);
            *(uint4*)&As_l[r][lk] = *(const uint4*)(Al + (size_t)(m0 + r) * K + k0 + lk);
            *(uint4*)&Bs_h[r][lk] = *(const uint4*)(Bh + (size_t)(n0 + r) * K + k0 + lk);
            *(uint4*)&Bs_l[r][lk] = *(const uint4*)(Bl + (size_t)(n0 + r) * K + k0 + lk);
        }
        __syncthreads();
#pragma unroll
        for (int kk = 0; kk < 32; kk += 16) {
            uint_t ah[2][4], al[2][4], bh[4][2], blx[4][2];
#pragma unroll
            for (int mt = 0; mt < 2; mt++) {
                load_a_frag(ah[mt], As_h, wm * 32 + mt * 16, kk, lane);
                load_a_frag(al[mt], As_l, wm * 32 + mt * 16, kk, lane);
            }
#pragma unroll
            for (int nt = 0; nt < 4; nt++) {
                load_b_frag(bh[nt],  Bs_h, wn * 32 + nt * 8, kk, lane);
                load_b_frag(blx[nt], Bs_l, wn * 32 + nt * 8, kk, lane);
            }
#pragma unroll
            for (int mt = 0; mt < 2; mt++)
#pragma unroll
                for (int nt = 0; nt < 4; nt++) {
                    mma16816(acc[mt][nt], ah[mt], bh[nt]);
                    mma16816(acc[mt][nt], ah[mt], blx[nt]);
                    mma16816(acc[mt][nt], al[mt], bh[nt]);
                }
        }
        __syncthreads();
    }

#pragma unroll
    for (int mt = 0; mt < 2; mt++)
#pragma unroll
        for (int nt = 0; nt < 4; nt++) {
            int r  = m0 + wm * 32 + mt * 16 + (lane >> 2);
            int cg = n0 + wn * 32 + nt * 8 + (lane & 3) * 2;
            float b0 = bias[((cg & 3) << 10) | (cg >> 2)];
            float b1 = bias[(((cg + 1) & 3) << 10) | ((cg + 1) >> 2)];
            C[(size_t)r * Gn + cg]           = acc[mt][nt][0] + b0;
            C[(size_t)r * Gn + cg + 1]       = acc[mt][nt][1] + b1;
            C[(size_t)(r + 8) * Gn + cg]     = acc[mt][nt][2] + b0;
            C[(size_t)(r + 8) * Gn + cg + 1] = acc[mt][nt][3] + b1;
        }
}

// ---------------- persistent recurrence kernel ----------------
// grid (64, 1, 2) = 128 blocks (one per SM), 256 threads (8 warps).
// Block owns 64 n' columns (16 hidden units). warp w owns n' [w*8, w*8+8).
// U_hi for the block's 64 n' x K=1024 lives in smem for all 128 steps.
// U_lo lives in registers as persistent mma B-fragments.
// h passes between blocks through L2 (ldcg) with a per-step arrival counter.
// The spin-wait is BOUNDED: a genuine sync failure degrades to wrong results
// (visible rel_err) instead of a container-killing hang.

#define UH_STRIDE 1032
#define A_STRIDE  136
#define UH_ELEMS  (64 * UH_STRIDE)
#define A_ELEMS   (64 * A_STRIDE)
#define SMEM_USHORTS (UH_ELEMS + 4 * A_ELEMS)
#define SMEM_BYTES   (SMEM_USHORTS * 2)

extern __shared__ ushort_t s_mem[];

__global__ void __launch_bounds__(256, 1) lstm_layer(int layer, float* __restrict__ out)
{
    const int z    = blockIdx.z;
    const int nblk = blockIdx.x;
    const int tid  = threadIdx.x;
    const int lane = tid & 31;
    const int warp = tid >> 5;
    const int n0   = nblk * 64;

    ushort_t* sUh    = s_mem;
    ushort_t* sAh0   = s_mem + UH_ELEMS;
    ushort_t* sAl0   = sAh0 + A_ELEMS;
    ushort_t* sAh1   = sAl0 + A_ELEMS;
    ushort_t* sAl1   = sAh1 + A_ELEMS;

    // ---- prologue: U_hi -> smem (coalesced) ----
    {
        const uint4* src = (const uint4*)(g_Ut_hi[layer][z] + (size_t)n0 * Hn);
        for (int i = tid; i < 64 * 128; i += 256) {
            int r = i >> 7, c = i & 127;
            *(uint4*)&sUh[r * UH_STRIDE + c * 8] = __ldg(src + r * 128 + c);
        }
    }
    // ---- prologue: U_lo fragments -> persistent registers ----
    uint_t bl[64][2];
    {
        const ushort_t* base = g_Ut_lo[layer][z]
            + (size_t)(n0 + warp * 8 + (lane >> 2)) * Hn + (lane & 3) * 2;
#pragma unroll
        for (int kt = 0; kt < 64; kt++) {
            bl[kt][0] = *(const uint_t*)(base + kt * 16);
            bl[kt][1] = *(const uint_t*)(base + kt * 16 + 8);
        }
    }
    __syncthreads();

    // ldmatrix lane-invariant address pieces
    const uint_t sUh_base = (uint_t)__cvta_generic_to_shared(sUh);
    const uint_t b_addr0 = sUh_base
        + (uint_t)(((warp * 8 + (lane & 7)) * UH_STRIDE + ((lane & 8) ? 8 : 0)) * 2);
    const int a_row  = (lane & 7) + ((lane & 8) ? 8 : 0);
    const int a_koff = (lane & 16) ? 8 : 0;
    const uint_t sAh_base[2] = { (uint_t)__cvta_generic_to_shared(sAh0),
                                 (uint_t)__cvta_generic_to_shared(sAh1) };
    const uint_t sAl_base[2] = { (uint_t)__cvta_generic_to_shared(sAl0),
                                 (uint_t)__cvta_generic_to_shared(sAl1) };
    ushort_t* sAhp[2] = { sAh0, sAh1 };
    ushort_t* sAlp[2] = { sAl0, sAl1 };

    // cell state in registers (even lanes own (h_idx, 8 batch rows))
    float creg[4][2];
#pragma unroll
    for (int mt = 0; mt < 4; mt++) { creg[mt][0] = 0.f; creg[mt][1] = 0.f; }

    const int cg    = (lane & 3) * 2;                    // 0,2,4,6
    const int h_idx = nblk * 16 + warp * 2 + (cg >> 2);  // valid when cg in {0,4}
    const bool ep   = ((lane & 1) == 0);

    long bail = 0;   // tid 0 only: set after a spin times out once

    for (int tstep = 0; tstep < Tn; tstep++) {
        const int buf = tstep & 1;
        const ushort_t* __restrict__ Ahg = g_hh_hi[buf][z];
        const ushort_t* __restrict__ Alg = g_hh_lo[buf][z];
        ushort_t* __restrict__ Hoh = g_hh_hi[buf ^ 1][z];
        ushort_t* __restrict__ Hol = g_hh_lo[buf ^ 1][z];
        const int t_eff = z ? (Tn - 1 - tstep) : tstep;
        const float* __restrict__ Zrow = g_Z[z] + (size_t)t_eff * Bn * Gn;

        // wait for all 64 blocks of this direction to finish step t-1 (bounded)
        if (tstep > 0) {
            if (tid == 0) {
                long limit = bail ? 1000 : 5000000L;
                long iter = 0;
                while (ldcg_i(&g_ctr[z * Tn + tstep - 1]) < 64) {
                    __nanosleep(64);
                    if (++iter > limit) { bail = 1; break; }
                }
            }
            __syncthreads();
        }

        float acc[4][4];
#pragma unroll
        for (int mt = 0; mt < 4; mt++)
#pragma unroll
            for (int i = 0; i < 4; i++) acc[mt][i] = 0.f;

        // ---- K loop: 8 chunks of 128 k, double-buffered with register prefetch ----
        uint4 ph[4], pl[4];
        {
#pragma unroll
            for (int q = 0; q < 4; q++) {
                int i = tid + q * 256;
                int r = i >> 4, c = (i & 15) * 8;
                ph[q] = __ldcg((const uint4*)(Ahg + r * Hn + c));
                pl[q] = __ldcg((const uint4*)(Alg + r * Hn + c));
            }
#pragma unroll
            for (int q = 0; q < 4; q++) {
                int i = tid + q * 256;
                int r = i >> 4, c = (i & 15) * 8;
                *(uint4*)&sAhp[0][r * A_STRIDE + c] = ph[q];
                *(uint4*)&sAlp[0][r * A_STRIDE + c] = pl[q];
            }
            __syncthreads();
        }
#pragma unroll
        for (int ch = 0; ch < 8; ch++) {
            if (ch < 7) {
                const int k0 = (ch + 1) * 128;
#pragma unroll
                for (int q = 0; q < 4; q++) {
                    int i = tid + q * 256;
                    int r = i >> 4, c = (i & 15) * 8;
                    ph[q] = __ldcg((const uint4*)(Ahg + r * Hn + k0 + c));
                    pl[q] = __ldcg((const uint4*)(Alg + r * Hn + k0 + c));
                }
            }
            const int cb = ch & 1;
#pragma unroll
            for (int kl = 0; kl < 8; kl++) {
                const int kt = ch * 8 + kl;
                uint_t bh[2];
                ldsm2(bh, b_addr0 + kt * 32);
#pragma unroll
                for (int mt = 0; mt < 4; mt++) {
                    uint_t ah[4], al[4];
                    uint_t aoff = (uint_t)(((mt * 16 + a_row) * A_STRIDE
                                            + kl * 16 + a_koff) * 2);
                    ldsm4(ah, sAh_base[cb] + aoff);
                    ldsm4(al, sAl_base[cb] + aoff);
                    mma16816(acc[mt], ah, bh);
                    mma16816(acc[mt], al, bh);
                    mma16816(acc[mt], ah, bl[kt]);
                }
            }
            if (ch < 7) {
                const int pb = (ch + 1) & 1;
#pragma unroll
                for (int q = 0; q < 4; q++) {
                    int i = tid + q * 256;
                    int r = i >> 4, c = (i & 15) * 8;
                    *(uint4*)&sAhp[pb][r * A_STRIDE + c] = ph[q];
                    *(uint4*)&sAlp[pb][r * A_STRIDE + c] = pl[q];
                }
            }
            __syncthreads();
        }

        // ---- epilogue: gate combine + state update ----
#pragma unroll
        for (int mt = 0; mt < 4; mt++) {
            float p0 = __shfl_xor_sync(0xffffffffu, acc[mt][0], 1);
            float p1 = __shfl_xor_sync(0xffffffffu, acc[mt][1], 1);
            float p2 = __shfl_xor_sync(0xffffffffu, acc[mt][2], 1);
            float p3 = __shfl_xor_sync(0xffffffffu, acc[mt][3], 1);
            if (ep) {
#pragma unroll
                for (int rr = 0; rr < 2; rr++) {
                    int b = mt * 16 + (lane >> 2) + rr * 8;
                    float ui = rr ? acc[mt][2] : acc[mt][0];
                    float uf = rr ? acc[mt][3] : acc[mt][1];
                    float ug = rr ? p2 : p0;
                    float uo = rr ? p3 : p1;
                    float4 z4 = __ldg((const float4*)(Zrow + (size_t)b * Gn + (h_idx << 2)));
                    float ig = sigmoidf_(z4.x + ui);
                    float fg = sigmoidf_(z4.y + uf);
                    float gg = tanhf(z4.z + ug);
                    float og = sigmoidf_(z4.w + uo);
                    float cn = fg * creg[mt][rr] + ig * gg;
                    creg[mt][rr] = cn;
                    float hv = og * tanhf(cn);
                    ushort_t hh, hl; split_bf16(hv, hh, hl);
                    Hoh[b * Hn + h_idx] = hh;
                    Hol[b * Hn + h_idx] = hl;
                    if (layer == 0) {
                        size_t o = (size_t)(t_eff * Bn + b) * Hn + h_idx;
                        g_H0_hi[z][o] = hh;
                        g_H0_lo[z][o] = hl;
                    } else {
                        out[(size_t)b * Tn * 2 * Hn + (size_t)t_eff * 2 * Hn
                            + (size_t)z * Hn + h_idx] = hv;
                    }
                    if (z == 0 && tstep == Tn - 1) {
                        size_t bse = (size_t)Bn * Tn * 2 * Hn
                                   + (size_t)layer * 2 * Bn * Hn;
                        out[bse + (size_t)b * Hn + h_idx] = hv;
                        out[bse + (size_t)Bn * Hn + (size_t)b * Hn + h_idx] = cn;
                    }
                }
            }
        }

        __threadfence();
        __syncthreads();
        if (tid == 0) atomicAdd(&g_ctr[z * Tn + tstep], 1);
    }
}

// ---------------- launch ----------------
extern "C" void kernel_launch(void* const* d_in, const int* in_sizes, int n_in,
                              void* d_out, int out_size)
{
    (void)in_sizes; (void)n_in; (void)out_size;
    const int*   tokens = (const int*)  d_in[0];
    const float* emb    = (const float*)d_in[1];
    const float* W_f0   = (const float*)d_in[2];
    const float* U_f0   = (const float*)d_in[3];
    const float* b_f0   = (const float*)d_in[4];
    const float* W_f1   = (const float*)d_in[5];
    const float* U_f1   = (const float*)d_in[6];
    const float* b_f1   = (const float*)d_in[7];
    const float* W_b0   = (const float*)d_in[8];
    const float* U_b0   = (const float*)d_in[9];
    const float* b_b0   = (const float*)d_in[10];
    const float* W_b1   = (const float*)d_in[11];
    const float* U_b1   = (const float*)d_in[12];
    const float* b_b1   = (const float*)d_in[13];
    float* out = (float*)d_out;

    cudaFuncSetAttribute(lstm_layer, cudaFuncAttributeMaxDynamicSharedMemorySize,
                         SMEM_BYTES);

    ushort_t *wt0h, *wt0l, *wt1h, *wt1l, *uth, *utl;
    cudaGetSymbolAddress((void**)&wt0h, g_Wt0_hi);
    cudaGetSymbolAddress((void**)&wt0l, g_Wt0_lo);
    cudaGetSymbolAddress((void**)&wt1h, g_Wt1_hi);
    cudaGetSymbolAddress((void**)&wt1l, g_Wt1_lo);
    cudaGetSymbolAddress((void**)&uth,  g_Ut_hi);
    cudaGetSymbolAddress((void**)&utl,  g_Ut_lo);

    dim3 cb(32, 8);
    conv_wt<<<dim3(En / 32, Gn / 32), cb>>>(W_f0, wt0h,             wt0l,             En);
    conv_wt<<<dim3(En / 32, Gn / 32), cb>>>(W_b0, wt0h + Gn * En,   wt0l + Gn * En,   En);
    conv_wt<<<dim3(Hn / 32, Gn / 32), cb>>>(W_f1, wt1h,             wt1l,             Hn);
    conv_wt<<<dim3(Hn / 32, Gn / 32), cb>>>(W_b1, wt1h + Gn * Hn,   wt1l + Gn * Hn,   Hn);
    conv_wt<<<dim3(Hn / 32, Gn / 32), cb>>>(U_f0, uth,               utl,               Hn);
    conv_wt<<<dim3(Hn / 32, Gn / 32), cb>>>(U_b0, uth + Gn * Hn,     utl + Gn * Hn,     Hn);
    conv_wt<<<dim3(Hn / 32, Gn / 32), cb>>>(U_f1, uth + 2 * Gn * Hn, utl + 2 * Gn * Hn, Hn);
    conv_wt<<<dim3(Hn / 32, Gn / 32), cb>>>(U_b1, uth + 3 * Gn * Hn, utl + 3 * Gn * Hn, Hn);

    embed_split<<<Mrows, 128>>>(tokens, emb);

    gemm_mma<<<dim3(Mrows / 64, Gn / 64, 2), 128>>>(0, b_f0, b_b0);

    zero_state<<<(Bn * Hn + 255) / 256, 256>>>();
    lstm_layer<<<dim3(64, 1, 2), 256, SMEM_BYTES>>>(0, out);

    gemm_mma<<<dim3(Mrows / 64, Gn / 64, 2), 128>>>(1, b_f1, b_b1);

    zero_state<<<(Bn * Hn + 255) / 256, 256>>>();
    lstm_layer<<<dim3(64, 1, 2), 256, SMEM_BYTES>>>(1, out);
}

// round 8
// speedup vs baseline: 2.7941x; 1.1234x over previous
#include <cuda_runtime.h>
#include <cuda_bf16.h>
#include <math.h>

// Bidirectional 2-layer LSTM encoder — split-bf16 legacy mma.sync (sm_100 base target;
// tcgen05 rejected by harness ptxas). Persistent grid-synced recurrence.
// B=64, T=128, E=512, H=1024.  Gate order (Keras): i, f, g, o.
// Gate-interleaved column space: n' = h*4 + g.

#define Tn 128
#define Bn 64
#define En 512
#define Hn 1024
#define Gn 4096
#define Mrows (Tn*Bn)

typedef unsigned short ushort_t;
typedef unsigned int   uint_t;

// ---------------- static device scratch ----------------
__device__ ushort_t g_X_hi [Mrows * En];
__device__ ushort_t g_X_lo [Mrows * En];
__device__ float    g_Z    [2][Mrows * Gn];          // [dir][row][n'] fp32, bias folded
__device__ ushort_t g_H0_hi[2][Mrows * Hn];
__device__ ushort_t g_H0_lo[2][Mrows * Hn];
__device__ ushort_t g_hh_hi[2][2][Bn * Hn];          // [buf][dir]
__device__ ushort_t g_hh_lo[2][2][Bn * Hn];
__device__ int      g_ctr  [2 * Tn];                 // [dir][t] arrival counters
__device__ float    g_biasp[2][2][Gn];               // [layer][dir][n'] permuted bias

__device__ ushort_t g_Wt0_hi[2][Gn * En];
__device__ ushort_t g_Wt0_lo[2][Gn * En];
__device__ ushort_t g_Wt1_hi[2][Gn * Hn];
__device__ ushort_t g_Wt1_lo[2][Gn * Hn];
__device__ ushort_t g_Ut_hi [2][2][Gn * Hn];         // [layer][dir], [n'][K]
__device__ ushort_t g_Ut_lo [2][2][Gn * Hn];

// ---------------- helpers ----------------
__device__ __forceinline__ void split_bf16(float v, ushort_t& hi, ushort_t& lo)
{
    __nv_bfloat16 h = __float2bfloat16(v);
    float r = v - __bfloat162float(h);
    __nv_bfloat16 l = __float2bfloat16(r);
    hi = *reinterpret_cast<ushort_t*>(&h);
    lo = *reinterpret_cast<ushort_t*>(&l);
}

__device__ __forceinline__ void mma16816(float* c, const uint_t* a, const uint_t* b)
{
    asm volatile(
        "mma.sync.aligned.m16n8k16.row.col.f32.bf16.bf16.f32 "
        "{%0,%1,%2,%3}, {%4,%5,%6,%7}, {%8,%9}, {%0,%1,%2,%3};\n"
        : "+f"(c[0]), "+f"(c[1]), "+f"(c[2]), "+f"(c[3])
        : "r"(a[0]), "r"(a[1]), "r"(a[2]), "r"(a[3]), "r"(b[0]), "r"(b[1]));
}

__device__ __forceinline__ void ldsm4(uint_t* a, uint_t saddr)
{
    asm volatile("ldmatrix.sync.aligned.m8n8.x4.shared.b16 {%0,%1,%2,%3}, [%4];"
        : "=r"(a[0]), "=r"(a[1]), "=r"(a[2]), "=r"(a[3]) : "r"(saddr));
}
__device__ __forceinline__ void ldsm2(uint_t* b, uint_t saddr)
{
    asm volatile("ldmatrix.sync.aligned.m8n8.x2.shared.b16 {%0,%1}, [%2];"
        : "=r"(b[0]), "=r"(b[1]) : "r"(saddr));
}

__device__ __forceinline__ void cp16(uint_t saddr, const void* gaddr)
{
    asm volatile("cp.async.cg.shared.global [%0], [%1], 16;"
        :: "r"(saddr), "l"(gaddr));
}
__device__ __forceinline__ void cp_commit()
{
    asm volatile("cp.async.commit_group;");
}
template<int N> __device__ __forceinline__ void cp_wait()
{
    asm volatile("cp.async.wait_group %0;" :: "n"(N));
}

__device__ __forceinline__ int ldcg_i(const int* p)
{
    int v; asm volatile("ld.global.cg.b32 %0, [%1];" : "=r"(v) : "l"(p)); return v;
}

__device__ __forceinline__ float sigmoidf_(float x) { return 1.f / (1.f + __expf(-x)); }

// ---------------- weight conversion (2 dirs per launch): fp32 [K][4096] -> bf16 hi/lo [n'][K]
__global__ void conv_wt2(const float* __restrict__ s0, const float* __restrict__ s1,
                         ushort_t* __restrict__ dhi, ushort_t* __restrict__ dlo, int K)
{
    const float* __restrict__ src = blockIdx.z ? s1 : s0;
    ushort_t* __restrict__ dh = dhi + (size_t)blockIdx.z * Gn * K;
    ushort_t* __restrict__ dl = dlo + (size_t)blockIdx.z * Gn * K;
    __shared__ float tile[32][33];
    int k0 = blockIdx.x * 32;
    int n0 = blockIdx.y * 32;
    int tx = threadIdx.x, ty = threadIdx.y;
#pragma unroll
    for (int j = 0; j < 4; j++)
        tile[ty + j * 8][tx] = src[(size_t)(k0 + ty + j * 8) * Gn + n0 + tx];
    __syncthreads();
#pragma unroll
    for (int j = 0; j < 4; j++) {
        int b = ty + j * 8;
        int n = n0 + b;
        int np = ((n & 1023) << 2) | (n >> 10);   // n' = h*4 + g
        float v = tile[tx][b];
        ushort_t hi, lo; split_bf16(v, hi, lo);
        dh[(size_t)np * K + k0 + tx] = hi;
        dl[(size_t)np * K + k0 + tx] = lo;
    }
}

// ---------------- embedding gather + split ----------------
__global__ void embed_split(const int* __restrict__ tokens, const float* __restrict__ emb)
{
    int row = blockIdx.x;          // t*Bn + b
    int t = row >> 6, b = row & 63;
    int tok = tokens[b * Tn + t];
    const float4* src = (const float4*)(emb + (size_t)tok * En);
    for (int i = threadIdx.x; i < En / 4; i += blockDim.x) {
        float4 v = src[i];
        ushort_t h0,l0,h1,l1,h2,l2,h3,l3;
        split_bf16(v.x,h0,l0); split_bf16(v.y,h1,l1);
        split_bf16(v.z,h2,l2); split_bf16(v.w,h3,l3);
        size_t o = (size_t)row * En + i * 4;
        g_X_hi[o]=h0; g_X_hi[o+1]=h1; g_X_hi[o+2]=h2; g_X_hi[o+3]=h3;
        g_X_lo[o]=l0; g_X_lo[o+1]=l1; g_X_lo[o+2]=l2; g_X_lo[o+3]=l3;
    }
}

// ---------------- zero state (+ counters) ----------------
__global__ void zero_state()
{
    int i = blockIdx.x * blockDim.x + threadIdx.x;
    if (i < Bn * Hn) {
        g_hh_hi[0][0][i]=0; g_hh_hi[0][1][i]=0; g_hh_hi[1][0][i]=0; g_hh_hi[1][1][i]=0;
        g_hh_lo[0][0][i]=0; g_hh_lo[0][1][i]=0; g_hh_lo[1][0][i]=0; g_hh_lo[1][1][i]=0;
    }
    if (blockIdx.x == 0 && threadIdx.x < 2 * Tn) g_ctr[threadIdx.x] = 0;
}

// zero state + counters + permuted bias (one launch)
__global__ void init_misc(const float* __restrict__ bf0, const float* __restrict__ bb0,
                          const float* __restrict__ bf1, const float* __restrict__ bb1)
{
    int i = blockIdx.x * blockDim.x + threadIdx.x;
    if (i < Bn * Hn) {
        g_hh_hi[0][0][i]=0; g_hh_hi[0][1][i]=0; g_hh_hi[1][0][i]=0; g_hh_hi[1][1][i]=0;
        g_hh_lo[0][0][i]=0; g_hh_lo[0][1][i]=0; g_hh_lo[1][0][i]=0; g_hh_lo[1][1][i]=0;
    }
    if (i < 2 * Tn) g_ctr[i] = 0;
    if (i < Gn) {
        int orig = ((i & 3) << 10) | (i >> 2);
        g_biasp[0][0][i] = bf0[orig];
        g_biasp[0][1][i] = bb0[orig];
        g_biasp[1][0][i] = bf1[orig];
        g_biasp[1][1][i] = bb1[orig];
    }
}

// ---------------- projection GEMM: Z = A @ Wt^T + bias ----------------
// 128x128 block tile, BK=32, 256 threads (8 warps as 4m x 2n, warp tile 32x64).
// cp.async double-buffered.  Split-bf16: 3 mma products with fp32 accum.
#define GB_TILE 10240                       // 128 rows * 40 halves * 2B
#define GB_BUF  (4 * GB_TILE)               // Ah, Al, Bh, Bl
#define GB_SMEM (2 * GB_BUF)                // 80 KB

extern __shared__ char gb_smem[];

__global__ void __launch_bounds__(256) gemm_mma2(int layer)
{
    const int z = blockIdx.z;
    const int K = layer ? Hn : En;
    const ushort_t* __restrict__ Ah = layer ? g_H0_hi[z] : g_X_hi;
    const ushort_t* __restrict__ Al = layer ? g_H0_lo[z] : g_X_lo;
    const ushort_t* __restrict__ Bh = layer ? g_Wt1_hi[z] : g_Wt0_hi[z];
    const ushort_t* __restrict__ Bl = layer ? g_Wt1_lo[z] : g_Wt0_lo[z];
    const float* __restrict__ biasp = g_biasp[layer][z];
    float* __restrict__ C = g_Z[z];

    const int m0 = blockIdx.x * 128;
    const int n0 = blockIdx.y * 128;
    const int tid  = threadIdx.x;
    const int lane = tid & 31;
    const int warp = tid >> 5;
    const int wm = warp >> 1;       // 0..3
    const int wn = warp & 1;        // 0..1

    const uint_t sbase = (uint_t)__cvta_generic_to_shared(gb_smem);
    const size_t rowbytes = (size_t)K * 2;
    const char* gA_h = (const char*)(Ah + (size_t)m0 * K);
    const char* gA_l = (const char*)(Al + (size_t)m0 * K);
    const char* gB_h = (const char*)(Bh + (size_t)n0 * K);
    const char* gB_l = (const char*)(Bl + (size_t)n0 * K);

    // per-thread load mapping: 2 16B lines per tile
    const int l0row[2] = { tid >> 2, (tid + 256) >> 2 };
    const int l0c16[2] = { (tid & 3) * 16, (tid & 3) * 16 };

    auto issue_chunk = [&](int ch, int buf) {
        const size_t kbyte = (size_t)ch * 64;            // BK=32 halves = 64B
        const uint_t sb = sbase + buf * GB_BUF;
#pragma unroll
        for (int q = 0; q < 2; q++) {
            const int row = l0row[q];
            const int c16 = l0c16[q];
            const uint_t so = (uint_t)(row * 80 + c16);
            const size_t go = (size_t)row * rowbytes + kbyte + c16;
            cp16(sb + so,               gA_h + go);
            cp16(sb + GB_TILE + so,     gA_l + go);
            cp16(sb + 2 * GB_TILE + so, gB_h + go);
            cp16(sb + 3 * GB_TILE + so, gB_l + go);
        }
        cp_commit();
    };

    // ldmatrix per-lane address pieces (halves -> bytes *2)
    const int a_row  = (lane & 15);
    const int a_koff = (lane & 16) ? 8 : 0;
    const int b_row  = (lane & 7) + ((lane & 16) ? 8 : 0);
    const int b_koff = (lane & 8) ? 8 : 0;

    float acc[2][8][4];
#pragma unroll
    for (int mt = 0; mt < 2; mt++)
#pragma unroll
        for (int nt = 0; nt < 8; nt++)
#pragma unroll
            for (int i = 0; i < 4; i++) acc[mt][nt][i] = 0.f;

    const int nch = K / 32;
    issue_chunk(0, 0);
    for (int ch = 0; ch < nch; ch++) {
        if (ch + 1 < nch) { issue_chunk(ch + 1, (ch + 1) & 1); cp_wait<1>(); }
        else cp_wait<0>();
        __syncthreads();

        const uint_t sb = sbase + (ch & 1) * GB_BUF;
#pragma unroll
        for (int kk = 0; kk < 32; kk += 16) {
            uint_t ah[2][4], al[2][4], bh[8][2], bl[8][2];
#pragma unroll
            for (int mt = 0; mt < 2; mt++) {
                uint_t ao = (uint_t)(((wm * 32 + mt * 16 + a_row) * 40
                                      + kk + a_koff) * 2);
                ldsm4(ah[mt], sb + ao);
                ldsm4(al[mt], sb + GB_TILE + ao);
            }
#pragma unroll
            for (int np = 0; np < 4; np++) {
                uint_t bo = (uint_t)(((wn * 64 + np * 16 + b_row) * 40
                                      + kk + b_koff) * 2);
                uint_t t4[4];
                ldsm4(t4, sb + 2 * GB_TILE + bo);
                bh[np*2][0]=t4[0]; bh[np*2][1]=t4[1];
                bh[np*2+1][0]=t4[2]; bh[np*2+1][1]=t4[3];
                ldsm4(t4, sb + 3 * GB_TILE + bo);
                bl[np*2][0]=t4[0]; bl[np*2][1]=t4[1];
                bl[np*2+1][0]=t4[2]; bl[np*2+1][1]=t4[3];
            }
#pragma unroll
            for (int mt = 0; mt < 2; mt++)
#pragma unroll
                for (int nt = 0; nt < 8; nt++) {
                    mma16816(acc[mt][nt], ah[mt], bh[nt]);
                    mma16816(acc[mt][nt], ah[mt], bl[nt]);
                    mma16816(acc[mt][nt], al[mt], bh[nt]);
                }
        }
        __syncthreads();
    }

    // epilogue
#pragma unroll
    for (int mt = 0; mt < 2; mt++)
#pragma unroll
        for (int nt = 0; nt < 8; nt++) {
            int r = m0 + wm * 32 + mt * 16 + (lane >> 2);
            int c = n0 + wn * 64 + nt * 8 + (lane & 3) * 2;
            float b0 = biasp[c], b1 = biasp[c + 1];
            float2 o0 = { acc[mt][nt][0] + b0, acc[mt][nt][1] + b1 };
            float2 o1 = { acc[mt][nt][2] + b0, acc[mt][nt][3] + b1 };
            *(float2*)(C + (size_t)r * Gn + c)       = o0;
            *(float2*)(C + (size_t)(r + 8) * Gn + c) = o1;
        }
}

// ---------------- persistent recurrence kernel (identical to passing R6) ----------------
#define UH_STRIDE 1032
#define A_STRIDE  136
#define UH_ELEMS  (64 * UH_STRIDE)
#define A_ELEMS   (64 * A_STRIDE)
#define SMEM_USHORTS (UH_ELEMS + 4 * A_ELEMS)
#define SMEM_BYTES   (SMEM_USHORTS * 2)

extern __shared__ ushort_t s_mem[];

__global__ void __launch_bounds__(256, 1) lstm_layer(int layer, float* __restrict__ out)
{
    const int z    = blockIdx.z;
    const int nblk = blockIdx.x;
    const int tid  = threadIdx.x;
    const int lane = tid & 31;
    const int warp = tid >> 5;
    const int n0   = nblk * 64;

    ushort_t* sUh    = s_mem;
    ushort_t* sAh0   = s_mem + UH_ELEMS;
    ushort_t* sAl0   = sAh0 + A_ELEMS;
    ushort_t* sAh1   = sAl0 + A_ELEMS;
    ushort_t* sAl1   = sAh1 + A_ELEMS;

    {
        const uint4* src = (const uint4*)(g_Ut_hi[layer][z] + (size_t)n0 * Hn);
        for (int i = tid; i < 64 * 128; i += 256) {
            int r = i >> 7, c = i & 127;
            *(uint4*)&sUh[r * UH_STRIDE + c * 8] = __ldg(src + r * 128 + c);
        }
    }
    uint_t bl[64][2];
    {
        const ushort_t* base = g_Ut_lo[layer][z]
            + (size_t)(n0 + warp * 8 + (lane >> 2)) * Hn + (lane & 3) * 2;
#pragma unroll
        for (int kt = 0; kt < 64; kt++) {
            bl[kt][0] = *(const uint_t*)(base + kt * 16);
            bl[kt][1] = *(const uint_t*)(base + kt * 16 + 8);
        }
    }
    __syncthreads();

    const uint_t sUh_base = (uint_t)__cvta_generic_to_shared(sUh);
    const uint_t b_addr0 = sUh_base
        + (uint_t)(((warp * 8 + (lane & 7)) * UH_STRIDE + ((lane & 8) ? 8 : 0)) * 2);
    const int a_row  = (lane & 7) + ((lane & 8) ? 8 : 0);
    const int a_koff = (lane & 16) ? 8 : 0;
    const uint_t sAh_base[2] = { (uint_t)__cvta_generic_to_shared(sAh0),
                                 (uint_t)__cvta_generic_to_shared(sAh1) };
    const uint_t sAl_base[2] = { (uint_t)__cvta_generic_to_shared(sAl0),
                                 (uint_t)__cvta_generic_to_shared(sAl1) };
    ushort_t* sAhp[2] = { sAh0, sAh1 };
    ushort_t* sAlp[2] = { sAl0, sAl1 };

    float creg[4][2];
#pragma unroll
    for (int mt = 0; mt < 4; mt++) { creg[mt][0] = 0.f; creg[mt][1] = 0.f; }

    const int cg    = (lane & 3) * 2;
    const int h_idx = nblk * 16 + warp * 2 + (cg >> 2);
    const bool ep   = ((lane & 1) == 0);

    long bail = 0;

    for (int tstep = 0; tstep < Tn; tstep++) {
        const int buf = tstep & 1;
        const ushort_t* __restrict__ Ahg = g_hh_hi[buf][z];
        const ushort_t* __restrict__ Alg = g_hh_lo[buf][z];
        ushort_t* __restrict__ Hoh = g_hh_hi[buf ^ 1][z];
        ushort_t* __restrict__ Hol = g_hh_lo[buf ^ 1][z];
        const int t_eff = z ? (Tn - 1 - tstep) : tstep;
        const float* __restrict__ Zrow = g_Z[z] + (size_t)t_eff * Bn * Gn;

        if (tstep > 0) {
            if (tid == 0) {
                long limit = bail ? 1000 : 5000000L;
                long iter = 0;
                while (ldcg_i(&g_ctr[z * Tn + tstep - 1]) < 64) {
                    __nanosleep(64);
                    if (++iter > limit) { bail = 1; break; }
                }
            }
            __syncthreads();
        }

        float acc[4][4];
#pragma unroll
        for (int mt = 0; mt < 4; mt++)
#pragma unroll
            for (int i = 0; i < 4; i++) acc[mt][i] = 0.f;

        uint4 ph[4], pl[4];
        {
#pragma unroll
            for (int q = 0; q < 4; q++) {
                int i = tid + q * 256;
                int r = i >> 4, c = (i & 15) * 8;
                ph[q] = __ldcg((const uint4*)(Ahg + r * Hn + c));
                pl[q] = __ldcg((const uint4*)(Alg + r * Hn + c));
            }
#pragma unroll
            for (int q = 0; q < 4; q++) {
                int i = tid + q * 256;
                int r = i >> 4, c = (i & 15) * 8;
                *(uint4*)&sAhp[0][r * A_STRIDE + c] = ph[q];
                *(uint4*)&sAlp[0][r * A_STRIDE + c] = pl[q];
            }
            __syncthreads();
        }
#pragma unroll
        for (int ch = 0; ch < 8; ch++) {
            if (ch < 7) {
                const int k0 = (ch + 1) * 128;
#pragma unroll
                for (int q = 0; q < 4; q++) {
                    int i = tid + q * 256;
                    int r = i >> 4, c = (i & 15) * 8;
                    ph[q] = __ldcg((const uint4*)(Ahg + r * Hn + k0 + c));
                    pl[q] = __ldcg((const uint4*)(Alg + r * Hn + k0 + c));
                }
            }
            const int cb = ch & 1;
#pragma unroll
            for (int kl = 0; kl < 8; kl++) {
                const int kt = ch * 8 + kl;
                uint_t bh[2];
                ldsm2(bh, b_addr0 + kt * 32);
#pragma unroll
                for (int mt = 0; mt < 4; mt++) {
                    uint_t ah[4], al[4];
                    uint_t aoff = (uint_t)(((mt * 16 + a_row) * A_STRIDE
                                            + kl * 16 + a_koff) * 2);
                    ldsm4(ah, sAh_base[cb] + aoff);
                    ldsm4(al, sAl_base[cb] + aoff);
                    mma16816(acc[mt], ah, bh);
                    mma16816(acc[mt], al, bh);
                    mma16816(acc[mt], ah, bl[kt]);
                }
            }
            if (ch < 7) {
                const int pb = (ch + 1) & 1;
#pragma unroll
                for (int q = 0; q < 4; q++) {
                    int i = tid + q * 256;
                    int r = i >> 4, c = (i & 15) * 8;
                    *(uint4*)&sAhp[pb][r * A_STRIDE + c] = ph[q];
                    *(uint4*)&sAlp[pb][r * A_STRIDE + c] = pl[q];
                }
            }
            __syncthreads();
        }

#pragma unroll
        for (int mt = 0; mt < 4; mt++) {
            float p0 = __shfl_xor_sync(0xffffffffu, acc[mt][0], 1);
            float p1 = __shfl_xor_sync(0xffffffffu, acc[mt][1], 1);
            float p2 = __shfl_xor_sync(0xffffffffu, acc[mt][2], 1);
            float p3 = __shfl_xor_sync(0xffffffffu, acc[mt][3], 1);
            if (ep) {
#pragma unroll
                for (int rr = 0; rr < 2; rr++) {
                    int b = mt * 16 + (lane >> 2) + rr * 8;
                    float ui = rr ? acc[mt][2] : acc[mt][0];
                    float uf = rr ? acc[mt][3] : acc[mt][1];
                    float ug = rr ? p2 : p0;
                    float uo = rr ? p3 : p1;
                    float4 z4 = __ldg((const float4*)(Zrow + (size_t)b * Gn + (h_idx << 2)));
                    float ig = sigmoidf_(z4.x + ui);
                    float fg = sigmoidf_(z4.y + uf);
                    float gg = tanhf(z4.z + ug);
                    float og = sigmoidf_(z4.w + uo);
                    float cn = fg * creg[mt][rr] + ig * gg;
                    creg[mt][rr] = cn;
                    float hv = og * tanhf(cn);
                    ushort_t hh, hl; split_bf16(hv, hh, hl);
                    Hoh[b * Hn + h_idx] = hh;
                    Hol[b * Hn + h_idx] = hl;
                    if (layer == 0) {
                        size_t o = (size_t)(t_eff * Bn + b) * Hn + h_idx;
                        g_H0_hi[z][o] = hh;
                        g_H0_lo[z][o] = hl;
                    } else {
                        out[(size_t)b * Tn * 2 * Hn + (size_t)t_eff * 2 * Hn
                            + (size_t)z * Hn + h_idx] = hv;
                    }
                    if (z == 0 && tstep == Tn - 1) {
                        size_t bse = (size_t)Bn * Tn * 2 * Hn
                                   + (size_t)layer * 2 * Bn * Hn;
                        out[bse + (size_t)b * Hn + h_idx] = hv;
                        out[bse + (size_t)Bn * Hn + (size_t)b * Hn + h_idx] = cn;
                    }
                }
            }
        }

        __threadfence();
        __syncthreads();
        if (tid == 0) atomicAdd(&g_ctr[z * Tn + tstep], 1);
    }
}

// ---------------- launch ----------------
extern "C" void kernel_launch(void* const* d_in, const int* in_sizes, int n_in,
                              void* d_out, int out_size)
{
    (void)in_sizes; (void)n_in; (void)out_size;
    const int*   tokens = (const int*)  d_in[0];
    const float* emb    = (const float*)d_in[1];
    const float* W_f0   = (const float*)d_in[2];
    const float* U_f0   = (const float*)d_in[3];
    const float* b_f0   = (const float*)d_in[4];
    const float* W_f1   = (const float*)d_in[5];
    const float* U_f1   = (const float*)d_in[6];
    const float* b_f1   = (const float*)d_in[7];
    const float* W_b0   = (const float*)d_in[8];
    const float* U_b0   = (const float*)d_in[9];
    const float* b_b0   = (const float*)d_in[10];
    const float* W_b1   = (const float*)d_in[11];
    const float* U_b1   = (const float*)d_in[12];
    const float* b_b1   = (const float*)d_in[13];
    float* out = (float*)d_out;

    cudaFuncSetAttribute(lstm_layer, cudaFuncAttributeMaxDynamicSharedMemorySize,
                         SMEM_BYTES);
    cudaFuncSetAttribute(gemm_mma2, cudaFuncAttributeMaxDynamicSharedMemorySize,
                         GB_SMEM);

    ushort_t *wt0h, *wt0l, *wt1h, *wt1l, *uth, *utl;
    cudaGetSymbolAddress((void**)&wt0h, g_Wt0_hi);
    cudaGetSymbolAddress((void**)&wt0l, g_Wt0_lo);
    cudaGetSymbolAddress((void**)&wt1h, g_Wt1_hi);
    cudaGetSymbolAddress((void**)&wt1l, g_Wt1_lo);
    cudaGetSymbolAddress((void**)&uth,  g_Ut_hi);
    cudaGetSymbolAddress((void**)&utl,  g_Ut_lo);

    dim3 cb(32, 8);
    // ncu uses -s 5 -c 1: launch index 5 must be lstm_layer(0).
    conv_wt2<<<dim3(En/32, Gn/32, 2), cb>>>(W_f0, W_b0, wt0h, wt0l, En);        // 0
    embed_split<<<Mrows, 128>>>(tokens, emb);                                   // 1
    conv_wt2<<<dim3(Hn/32, Gn/32, 2), cb>>>(U_f0, U_b0, uth, utl, Hn);          // 2
    init_misc<<<256, 256>>>(b_f0, b_b0, b_f1, b_b1);                            // 3
    gemm_mma2<<<dim3(Mrows/128, Gn/128, 2), 256, GB_SMEM>>>(0);                 // 4
    lstm_layer<<<dim3(64, 1, 2), 256, SMEM_BYTES>>>(0, out);                    // 5  <- ncu
    conv_wt2<<<dim3(Hn/32, Gn/32, 2), cb>>>(W_f1, W_b1, wt1h, wt1l, Hn);        // 6
    conv_wt2<<<dim3(Hn/32, Gn/32, 2), cb>>>(U_f1, U_b1,
                                            uth + 2 * (size_t)Gn * Hn,
                                            utl + 2 * (size_t)Gn * Hn, Hn);     // 7
    gemm_mma2<<<dim3(Mrows/128, Gn/128, 2), 256, GB_SMEM>>>(1);                 // 8
    zero_state<<<(Bn * Hn + 255) / 256, 256>>>();                               // 9
    lstm_layer<<<dim3(64, 1, 2), 256, SMEM_BYTES>>>(1, out);                    // 10
}

// round 9
// speedup vs baseline: 2.8400x; 1.0164x over previous
#include <cuda_runtime.h>
#include <cuda_bf16.h>
#include <math.h>

// Bidirectional 2-layer LSTM encoder — split-bf16 legacy mma.sync (sm_100 base
// target), persistent grid-synced recurrence.  B=64, T=128, E=512, H=1024.
// Keras gate order i,f,g,o.  Gate-interleaved column space: n' = h*4 + g.

#define Tn 128
#define Bn 64
#define En 512
#define Hn 1024
#define Gn 4096
#define Mrows (Tn*Bn)

typedef unsigned short ushort_t;
typedef unsigned int   uint_t;

// ---------------- static device scratch ----------------
__device__ ushort_t g_X_hi [Mrows * En];
__device__ ushort_t g_X_lo [Mrows * En];
__device__ float    g_Z    [2][Mrows * Gn];          // [dir][row][n'] fp32
__device__ ushort_t g_H0_hi[2][Mrows * Hn];
__device__ ushort_t g_H0_lo[2][Mrows * Hn];
__device__ ushort_t g_hh_hi[2][2][Bn * Hn];          // [buf][dir]
__device__ ushort_t g_hh_lo[2][2][Bn * Hn];
__device__ int      g_ctr  [2 * Tn];                 // [dir][t] arrival counters
__device__ float    g_biasp[2][2][Gn];               // [layer][dir][n']

__device__ ushort_t g_Wt0_hi[2][Gn * En];
__device__ ushort_t g_Wt0_lo[2][Gn * En];
__device__ ushort_t g_Wt1_hi[2][Gn * Hn];
__device__ ushort_t g_Wt1_lo[2][Gn * Hn];
__device__ ushort_t g_Ut_hi [2][2][Gn * Hn];         // [layer][dir], [n'][K]
__device__ ushort_t g_Ut_lo [2][2][Gn * Hn];

// ---------------- helpers ----------------
__device__ __forceinline__ void split_bf16(float v, ushort_t& hi, ushort_t& lo)
{
    __nv_bfloat16 h = __float2bfloat16(v);
    float r = v - __bfloat162float(h);
    __nv_bfloat16 l = __float2bfloat16(r);
    hi = *reinterpret_cast<ushort_t*>(&h);
    lo = *reinterpret_cast<ushort_t*>(&l);
}

__device__ __forceinline__ void mma16816(float* c, const uint_t* a, const uint_t* b)
{
    asm volatile(
        "mma.sync.aligned.m16n8k16.row.col.f32.bf16.bf16.f32 "
        "{%0,%1,%2,%3}, {%4,%5,%6,%7}, {%8,%9}, {%0,%1,%2,%3};\n"
        : "+f"(c[0]), "+f"(c[1]), "+f"(c[2]), "+f"(c[3])
        : "r"(a[0]), "r"(a[1]), "r"(a[2]), "r"(a[3]), "r"(b[0]), "r"(b[1]));
}

__device__ __forceinline__ void ldsm4(uint_t* a, uint_t saddr)
{
    asm volatile("ldmatrix.sync.aligned.m8n8.x4.shared.b16 {%0,%1,%2,%3}, [%4];"
        : "=r"(a[0]), "=r"(a[1]), "=r"(a[2]), "=r"(a[3]) : "r"(saddr));
}
__device__ __forceinline__ void ldsm2(uint_t* b, uint_t saddr)
{
    asm volatile("ldmatrix.sync.aligned.m8n8.x2.shared.b16 {%0,%1}, [%2];"
        : "=r"(b[0]), "=r"(b[1]) : "r"(saddr));
}

__device__ __forceinline__ void cp16(uint_t saddr, const void* gaddr)
{
    asm volatile("cp.async.cg.shared.global [%0], [%1], 16;"
        :: "r"(saddr), "l"(gaddr));
}
__device__ __forceinline__ void cp_commit()
{
    asm volatile("cp.async.commit_group;");
}
template<int N> __device__ __forceinline__ void cp_wait()
{
    asm volatile("cp.async.wait_group %0;" :: "n"(N));
}

__device__ __forceinline__ int ldcg_i(const int* p)
{
    int v; asm volatile("ld.global.cg.b32 %0, [%1];" : "=r"(v) : "l"(p)); return v;
}

__device__ __forceinline__ float sigmoidf_(float x) { return 1.f / (1.f + __expf(-x)); }

// ---------------- fused weight conversion (layer 0): W_f0,W_b0,U_f0,U_b0 ----------------
// z: 0 -> W_f0 (K=512), 1 -> W_b0 (K=512), 2 -> U_f0 (K=1024), 3 -> U_b0 (K=1024)
__global__ void conv_all0(const float* __restrict__ Wf0, const float* __restrict__ Wb0,
                          const float* __restrict__ Uf0, const float* __restrict__ Ub0)
{
    const int zi = blockIdx.z;
    const float* __restrict__ src;
    ushort_t *dh, *dl;
    int K;
    if (zi < 2) { K = En; src = zi ? Wb0 : Wf0; dh = g_Wt0_hi[zi]; dl = g_Wt0_lo[zi]; }
    else        { K = Hn; src = (zi == 3) ? Ub0 : Uf0;
                  dh = g_Ut_hi[0][zi - 2]; dl = g_Ut_lo[0][zi - 2]; }
    int k0 = blockIdx.x * 32;
    if (k0 >= K) return;
    int n0 = blockIdx.y * 32;
    int tx = threadIdx.x, ty = threadIdx.y;
    __shared__ float tile[32][33];
#pragma unroll
    for (int j = 0; j < 4; j++)
        tile[ty + j * 8][tx] = src[(size_t)(k0 + ty + j * 8) * Gn + n0 + tx];
    __syncthreads();
#pragma unroll
    for (int j = 0; j < 4; j++) {
        int b = ty + j * 8;
        int n = n0 + b;
        int np = ((n & 1023) << 2) | (n >> 10);   // n' = h*4 + g
        float v = tile[tx][b];
        ushort_t hi, lo; split_bf16(v, hi, lo);
        dh[(size_t)np * K + k0 + tx] = hi;
        dl[(size_t)np * K + k0 + tx] = lo;
    }
}

// ---------------- fused weight conversion (layer 1): W_f1,W_b1,U_f1,U_b1 (all K=1024)
__global__ void conv_all1(const float* __restrict__ Wf1, const float* __restrict__ Wb1,
                          const float* __restrict__ Uf1, const float* __restrict__ Ub1)
{
    const int zi = blockIdx.z;
    const float* __restrict__ src = (zi == 0) ? Wf1 : (zi == 1) ? Wb1
                                  : (zi == 2) ? Uf1 : Ub1;
    ushort_t* dh = (zi < 2) ? g_Wt1_hi[zi] : g_Ut_hi[1][zi - 2];
    ushort_t* dl = (zi < 2) ? g_Wt1_lo[zi] : g_Ut_lo[1][zi - 2];
    int k0 = blockIdx.x * 32;
    int n0 = blockIdx.y * 32;
    int tx = threadIdx.x, ty = threadIdx.y;
    __shared__ float tile[32][33];
#pragma unroll
    for (int j = 0; j < 4; j++)
        tile[ty + j * 8][tx] = src[(size_t)(k0 + ty + j * 8) * Gn + n0 + tx];
    __syncthreads();
#pragma unroll
    for (int j = 0; j < 4; j++) {
        int b = ty + j * 8;
        int n = n0 + b;
        int np = ((n & 1023) << 2) | (n >> 10);
        float v = tile[tx][b];
        ushort_t hi, lo; split_bf16(v, hi, lo);
        dh[(size_t)np * Hn + k0 + tx] = hi;
        dl[(size_t)np * Hn + k0 + tx] = lo;
    }
}

// ---------------- fused embedding + state zero + counter zero + bias permute ----------------
// blocks [0, Mrows): embedding gather+split.  blocks [Mrows, Mrows+256): init.
__global__ void embed_init(const int* __restrict__ tokens, const float* __restrict__ emb,
                           const float* __restrict__ bf0, const float* __restrict__ bb0,
                           const float* __restrict__ bf1, const float* __restrict__ bb1)
{
    if (blockIdx.x < Mrows) {
        int row = blockIdx.x;          // t*Bn + b
        int t = row >> 6, b = row & 63;
        int tok = tokens[b * Tn + t];
        const float4* src = (const float4*)(emb + (size_t)tok * En);
        for (int i = threadIdx.x; i < En / 4; i += blockDim.x) {
            float4 v = src[i];
            ushort_t h0,l0,h1,l1,h2,l2,h3,l3;
            split_bf16(v.x,h0,l0); split_bf16(v.y,h1,l1);
            split_bf16(v.z,h2,l2); split_bf16(v.w,h3,l3);
            size_t o = (size_t)row * En + i * 4;
            g_X_hi[o]=h0; g_X_hi[o+1]=h1; g_X_hi[o+2]=h2; g_X_hi[o+3]=h3;
            g_X_lo[o]=l0; g_X_lo[o+1]=l1; g_X_lo[o+2]=l2; g_X_lo[o+3]=l3;
        }
    } else {
        int blk = blockIdx.x - Mrows;  // 0..255
#pragma unroll
        for (int q = 0; q < 2; q++) {
            int i = blk * 256 + q * 128 + threadIdx.x;   // 0..65535
            g_hh_hi[0][0][i]=0; g_hh_hi[0][1][i]=0;
            g_hh_hi[1][0][i]=0; g_hh_hi[1][1][i]=0;
            g_hh_lo[0][0][i]=0; g_hh_lo[0][1][i]=0;
            g_hh_lo[1][0][i]=0; g_hh_lo[1][1][i]=0;
            if (i < 2 * Tn) g_ctr[i] = 0;
            if (i < Gn) {
                int orig = ((i & 3) << 10) | (i >> 2);
                g_biasp[0][0][i] = bf0[orig];
                g_biasp[0][1][i] = bb0[orig];
                g_biasp[1][0][i] = bf1[orig];
                g_biasp[1][1][i] = bb1[orig];
            }
        }
    }
}

// ---------------- zero state + counters (before layer-1 recurrence) ----------------
__global__ void zero_state()
{
    int i = blockIdx.x * blockDim.x + threadIdx.x;
    if (i < Bn * Hn) {
        g_hh_hi[0][0][i]=0; g_hh_hi[0][1][i]=0; g_hh_hi[1][0][i]=0; g_hh_hi[1][1][i]=0;
        g_hh_lo[0][0][i]=0; g_hh_lo[0][1][i]=0; g_hh_lo[1][0][i]=0; g_hh_lo[1][1][i]=0;
    }
    if (blockIdx.x == 0 && threadIdx.x < 2 * Tn) g_ctr[threadIdx.x] = 0;
}

// ---------------- projection GEMM: Z = A @ Wt^T + bias ----------------
// 128x128 block tile, BK=32, 256 threads (8 warps as 4m x 2n, warp tile 32x64).
// cp.async double-buffered.  Split-bf16: 3 mma products, fp32 accum.
#define GB_TILE 10240                       // 128 rows * 40 halves * 2B
#define GB_BUF  (4 * GB_TILE)
#define GB_SMEM (2 * GB_BUF)                // 80 KB

extern __shared__ char gb_smem[];

__global__ void __launch_bounds__(256) gemm_mma2(int layer)
{
    const int z = blockIdx.z;
    const int K = layer ? Hn : En;
    const ushort_t* __restrict__ Ah = layer ? g_H0_hi[z] : g_X_hi;
    const ushort_t* __restrict__ Al = layer ? g_H0_lo[z] : g_X_lo;
    const ushort_t* __restrict__ Bh = layer ? g_Wt1_hi[z] : g_Wt0_hi[z];
    const ushort_t* __restrict__ Bl = layer ? g_Wt1_lo[z] : g_Wt0_lo[z];
    const float* __restrict__ biasp = g_biasp[layer][z];
    float* __restrict__ C = g_Z[z];

    const int m0 = blockIdx.x * 128;
    const int n0 = blockIdx.y * 128;
    const int tid  = threadIdx.x;
    const int lane = tid & 31;
    const int warp = tid >> 5;
    const int wm = warp >> 1;
    const int wn = warp & 1;

    const uint_t sbase = (uint_t)__cvta_generic_to_shared(gb_smem);
    const size_t rowbytes = (size_t)K * 2;
    const char* gA_h = (const char*)(Ah + (size_t)m0 * K);
    const char* gA_l = (const char*)(Al + (size_t)m0 * K);
    const char* gB_h = (const char*)(Bh + (size_t)n0 * K);
    const char* gB_l = (const char*)(Bl + (size_t)n0 * K);

    const int l0row[2] = { tid >> 2, (tid + 256) >> 2 };
    const int l0c16   = (tid & 3) * 16;

    auto issue_chunk = [&](int ch, int buf) {
        const size_t kbyte = (size_t)ch * 64;
        const uint_t sb = sbase + buf * GB_BUF;
#pragma unroll
        for (int q = 0; q < 2; q++) {
            const int row = l0row[q];
            const uint_t so = (uint_t)(row * 80 + l0c16);
            const size_t go = (size_t)row * rowbytes + kbyte + l0c16;
            cp16(sb + so,               gA_h + go);
            cp16(sb + GB_TILE + so,     gA_l + go);
            cp16(sb + 2 * GB_TILE + so, gB_h + go);
            cp16(sb + 3 * GB_TILE + so, gB_l + go);
        }
        cp_commit();
    };

    const int a_row  = (lane & 15);
    const int a_koff = (lane & 16) ? 8 : 0;
    const int b_row  = (lane & 7) + ((lane & 16) ? 8 : 0);
    const int b_koff = (lane & 8) ? 8 : 0;

    float acc[2][8][4];
#pragma unroll
    for (int mt = 0; mt < 2; mt++)
#pragma unroll
        for (int nt = 0; nt < 8; nt++)
#pragma unroll
            for (int i = 0; i < 4; i++) acc[mt][nt][i] = 0.f;

    const int nch = K / 32;
    issue_chunk(0, 0);
    for (int ch = 0; ch < nch; ch++) {
        if (ch + 1 < nch) { issue_chunk(ch + 1, (ch + 1) & 1); cp_wait<1>(); }
        else cp_wait<0>();
        __syncthreads();

        const uint_t sb = sbase + (ch & 1) * GB_BUF;
#pragma unroll
        for (int kk = 0; kk < 32; kk += 16) {
            uint_t ah[2][4], al[2][4], bh[8][2], bl[8][2];
#pragma unroll
            for (int mt = 0; mt < 2; mt++) {
                uint_t ao = (uint_t)(((wm * 32 + mt * 16 + a_row) * 40
                                      + kk + a_koff) * 2);
                ldsm4(ah[mt], sb + ao);
                ldsm4(al[mt], sb + GB_TILE + ao);
            }
#pragma unroll
            for (int np = 0; np < 4; np++) {
                uint_t bo = (uint_t)(((wn * 64 + np * 16 + b_row) * 40
                                      + kk + b_koff) * 2);
                uint_t t4[4];
                ldsm4(t4, sb + 2 * GB_TILE + bo);
                bh[np*2][0]=t4[0]; bh[np*2][1]=t4[1];
                bh[np*2+1][0]=t4[2]; bh[np*2+1][1]=t4[3];
                ldsm4(t4, sb + 3 * GB_TILE + bo);
                bl[np*2][0]=t4[0]; bl[np*2][1]=t4[1];
                bl[np*2+1][0]=t4[2]; bl[np*2+1][1]=t4[3];
            }
#pragma unroll
            for (int mt = 0; mt < 2; mt++)
#pragma unroll
                for (int nt = 0; nt < 8; nt++) {
                    mma16816(acc[mt][nt], ah[mt], bh[nt]);
                    mma16816(acc[mt][nt], ah[mt], bl[nt]);
                    mma16816(acc[mt][nt], al[mt], bh[nt]);
                }
        }
        __syncthreads();
    }

#pragma unroll
    for (int mt = 0; mt < 2; mt++)
#pragma unroll
        for (int nt = 0; nt < 8; nt++) {
            int r = m0 + wm * 32 + mt * 16 + (lane >> 2);
            int c = n0 + wn * 64 + nt * 8 + (lane & 3) * 2;
            float b0 = biasp[c], b1 = biasp[c + 1];
            float2 o0 = { acc[mt][nt][0] + b0, acc[mt][nt][1] + b1 };
            float2 o1 = { acc[mt][nt][2] + b0, acc[mt][nt][3] + b1 };
            *(float2*)(C + (size_t)r * Gn + c)       = o0;
            *(float2*)(C + (size_t)(r + 8) * Gn + c) = o1;
        }
}

// ---------------- persistent recurrence kernel ----------------
// Split accumulators: acc (ah*bh) and acc2 (al*bh + ah*bl) — breaks the
// 3-deep RAW chain per k-tile into independent 1- and 2-chains.
#define UH_STRIDE 1032
#define A_STRIDE  136
#define UH_ELEMS  (64 * UH_STRIDE)
#define A_ELEMS   (64 * A_STRIDE)
#define SMEM_USHORTS (UH_ELEMS + 4 * A_ELEMS)
#define SMEM_BYTES   (SMEM_USHORTS * 2)

extern __shared__ ushort_t s_mem[];

__global__ void __launch_bounds__(256, 1) lstm_layer(int layer, float* __restrict__ out)
{
    const int z    = blockIdx.z;
    const int nblk = blockIdx.x;
    const int tid  = threadIdx.x;
    const int lane = tid & 31;
    const int warp = tid >> 5;
    const int n0   = nblk * 64;

    ushort_t* sUh    = s_mem;
    ushort_t* sAh0   = s_mem + UH_ELEMS;
    ushort_t* sAl0   = sAh0 + A_ELEMS;
    ushort_t* sAh1   = sAl0 + A_ELEMS;
    ushort_t* sAl1   = sAh1 + A_ELEMS;

    {
        const uint4* src = (const uint4*)(g_Ut_hi[layer][z] + (size_t)n0 * Hn);
        for (int i = tid; i < 64 * 128; i += 256) {
            int r = i >> 7, c = i & 127;
            *(uint4*)&sUh[r * UH_STRIDE + c * 8] = __ldg(src + r * 128 + c);
        }
    }
    uint_t bl[64][2];
    {
        const ushort_t* base = g_Ut_lo[layer][z]
            + (size_t)(n0 + warp * 8 + (lane >> 2)) * Hn + (lane & 3) * 2;
#pragma unroll
        for (int kt = 0; kt < 64; kt++) {
            bl[kt][0] = *(const uint_t*)(base + kt * 16);
            bl[kt][1] = *(const uint_t*)(base + kt * 16 + 8);
        }
    }
    __syncthreads();

    const uint_t sUh_base = (uint_t)__cvta_generic_to_shared(sUh);
    const uint_t b_addr0 = sUh_base
        + (uint_t)(((warp * 8 + (lane & 7)) * UH_STRIDE + ((lane & 8) ? 8 : 0)) * 2);
    const int a_row  = (lane & 7) + ((lane & 8) ? 8 : 0);
    const int a_koff = (lane & 16) ? 8 : 0;
    const uint_t sAh_base[2] = { (uint_t)__cvta_generic_to_shared(sAh0),
                                 (uint_t)__cvta_generic_to_shared(sAh1) };
    const uint_t sAl_base[2] = { (uint_t)__cvta_generic_to_shared(sAl0),
                                 (uint_t)__cvta_generic_to_shared(sAl1) };
    ushort_t* sAhp[2] = { sAh0, sAh1 };
    ushort_t* sAlp[2] = { sAl0, sAl1 };

    float creg[4][2];
#pragma unroll
    for (int mt = 0; mt < 4; mt++) { creg[mt][0] = 0.f; creg[mt][1] = 0.f; }

    const int cg    = (lane & 3) * 2;
    const int h_idx = nblk * 16 + warp * 2 + (cg >> 2);
    const bool ep   = ((lane & 1) == 0);

    long bail = 0;

    for (int tstep = 0; tstep < Tn; tstep++) {
        const int buf = tstep & 1;
        const ushort_t* __restrict__ Ahg = g_hh_hi[buf][z];
        const ushort_t* __restrict__ Alg = g_hh_lo[buf][z];
        ushort_t* __restrict__ Hoh = g_hh_hi[buf ^ 1][z];
        ushort_t* __restrict__ Hol = g_hh_lo[buf ^ 1][z];
        const int t_eff = z ? (Tn - 1 - tstep) : tstep;
        const float* __restrict__ Zrow = g_Z[z] + (size_t)t_eff * Bn * Gn;

        if (tstep > 0) {
            if (tid == 0) {
                long limit = bail ? 1000 : 5000000L;
                long iter = 0;
                while (ldcg_i(&g_ctr[z * Tn + tstep - 1]) < 64) {
                    __nanosleep(64);
                    if (++iter > limit) { bail = 1; break; }
                }
            }
            __syncthreads();
        }

        float acc[4][4], acc2[4][4];
#pragma unroll
        for (int mt = 0; mt < 4; mt++)
#pragma unroll
            for (int i = 0; i < 4; i++) { acc[mt][i] = 0.f; acc2[mt][i] = 0.f; }

        uint4 ph[4], pl[4];
        {
#pragma unroll
            for (int q = 0; q < 4; q++) {
                int i = tid + q * 256;
                int r = i >> 4, c = (i & 15) * 8;
                ph[q] = __ldcg((const uint4*)(Ahg + r * Hn + c));
                pl[q] = __ldcg((const uint4*)(Alg + r * Hn + c));
            }
#pragma unroll
            for (int q = 0; q < 4; q++) {
                int i = tid + q * 256;
                int r = i >> 4, c = (i & 15) * 8;
                *(uint4*)&sAhp[0][r * A_STRIDE + c] = ph[q];
                *(uint4*)&sAlp[0][r * A_STRIDE + c] = pl[q];
            }
            __syncthreads();
        }
#pragma unroll
        for (int ch = 0; ch < 8; ch++) {
            if (ch < 7) {
                const int k0 = (ch + 1) * 128;
#pragma unroll
                for (int q = 0; q < 4; q++) {
                    int i = tid + q * 256;
                    int r = i >> 4, c = (i & 15) * 8;
                    ph[q] = __ldcg((const uint4*)(Ahg + r * Hn + k0 + c));
                    pl[q] = __ldcg((const uint4*)(Alg + r * Hn + k0 + c));
                }
            }
            const int cb = ch & 1;
#pragma unroll
            for (int kl = 0; kl < 8; kl++) {
                const int kt = ch * 8 + kl;
                uint_t bh[2];
                ldsm2(bh, b_addr0 + kt * 32);
#pragma unroll
                for (int mt = 0; mt < 4; mt++) {
                    uint_t ah[4], al[4];
                    uint_t aoff = (uint_t)(((mt * 16 + a_row) * A_STRIDE
                                            + kl * 16 + a_koff) * 2);
                    ldsm4(ah, sAh_base[cb] + aoff);
                    ldsm4(al, sAl_base[cb] + aoff);
                    mma16816(acc[mt],  ah, bh);
                    mma16816(acc2[mt], al, bh);
                    mma16816(acc2[mt], ah, bl[kt]);
                }
            }
            if (ch < 7) {
                const int pb = (ch + 1) & 1;
#pragma unroll
                for (int q = 0; q < 4; q++) {
                    int i = tid + q * 256;
                    int r = i >> 4, c = (i & 15) * 8;
                    *(uint4*)&sAhp[pb][r * A_STRIDE + c] = ph[q];
                    *(uint4*)&sAlp[pb][r * A_STRIDE + c] = pl[q];
                }
            }
            __syncthreads();
        }

#pragma unroll
        for (int mt = 0; mt < 4; mt++) {
#pragma unroll
            for (int i = 0; i < 4; i++) acc[mt][i] += acc2[mt][i];
            float p0 = __shfl_xor_sync(0xffffffffu, acc[mt][0], 1);
            float p1 = __shfl_xor_sync(0xffffffffu, acc[mt][1], 1);
            float p2 = __shfl_xor_sync(0xffffffffu, acc[mt][2], 1);
            float p3 = __shfl_xor_sync(0xffffffffu, acc[mt][3], 1);
            if (ep) {
#pragma unroll
                for (int rr = 0; rr < 2; rr++) {
                    int b = mt * 16 + (lane >> 2) + rr * 8;
                    float ui = rr ? acc[mt][2] : acc[mt][0];
                    float uf = rr ? acc[mt][3] : acc[mt][1];
                    float ug = rr ? p2 : p0;
                    float uo = rr ? p3 : p1;
                    float4 z4 = __ldg((const float4*)(Zrow + (size_t)b * Gn + (h_idx << 2)));
                    float ig = sigmoidf_(z4.x + ui);
                    float fg = sigmoidf_(z4.y + uf);
                    float gg = tanhf(z4.z + ug);
                    float og = sigmoidf_(z4.w + uo);
                    float cn = fg * creg[mt][rr] + ig * gg;
                    creg[mt][rr] = cn;
                    float hv = og * tanhf(cn);
                    ushort_t hh, hl; split_bf16(hv, hh, hl);
                    Hoh[b * Hn + h_idx] = hh;
                    Hol[b * Hn + h_idx] = hl;
                    if (layer == 0) {
                        size_t o = (size_t)(t_eff * Bn + b) * Hn + h_idx;
                        g_H0_hi[z][o] = hh;
                        g_H0_lo[z][o] = hl;
                    } else {
                        out[(size_t)b * Tn * 2 * Hn + (size_t)t_eff * 2 * Hn
                            + (size_t)z * Hn + h_idx] = hv;
                    }
                    if (z == 0 && tstep == Tn - 1) {
                        size_t bse = (size_t)Bn * Tn * 2 * Hn
                                   + (size_t)layer * 2 * Bn * Hn;
                        out[bse + (size_t)b * Hn + h_idx] = hv;
                        out[bse + (size_t)Bn * Hn + (size_t)b * Hn + h_idx] = cn;
                    }
                }
            }
        }

        __threadfence();
        __syncthreads();
        if (tid == 0) atomicAdd(&g_ctr[z * Tn + tstep], 1);
    }
}

// ---------------- launch ----------------
extern "C" void kernel_launch(void* const* d_in, const int* in_sizes, int n_in,
                              void* d_out, int out_size)
{
    (void)in_sizes; (void)n_in; (void)out_size;
    const int*   tokens = (const int*)  d_in[0];
    const float* emb    = (const float*)d_in[1];
    const float* W_f0   = (const float*)d_in[2];
    const float* U_f0   = (const float*)d_in[3];
    const float* b_f0   = (const float*)d_in[4];
    const float* W_f1   = (const float*)d_in[5];
    const float* U_f1   = (const float*)d_in[6];
    const float* b_f1   = (const float*)d_in[7];
    const float* W_b0   = (const float*)d_in[8];
    const float* U_b0   = (const float*)d_in[9];
    const float* b_b0   = (const float*)d_in[10];
    const float* W_b1   = (const float*)d_in[11];
    const float* U_b1   = (const float*)d_in[12];
    const float* b_b1   = (const float*)d_in[13];
    float* out = (float*)d_out;

    cudaFuncSetAttribute(lstm_layer, cudaFuncAttributeMaxDynamicSharedMemorySize,
                         SMEM_BYTES);
    cudaFuncSetAttribute(gemm_mma2, cudaFuncAttributeMaxDynamicSharedMemorySize,
                         GB_SMEM);

    dim3 cb(32, 8);
    // harness issues 2 launches before these; ncu (-s 5 -c 1) profiles MY index 3.
    conv_all0<<<dim3(32, 128, 4), cb>>>(W_f0, W_b0, U_f0, U_b0);                // 0
    embed_init<<<Mrows + 256, 128>>>(tokens, emb, b_f0, b_b0, b_f1, b_b1);      // 1
    gemm_mma2<<<dim3(Mrows/128, Gn/128, 2), 256, GB_SMEM>>>(0);                 // 2
    lstm_layer<<<dim3(64, 1, 2), 256, SMEM_BYTES>>>(0, out);                    // 3  <- ncu
    conv_all1<<<dim3(32, 128, 4), cb>>>(W_f1, W_b1, U_f1, U_b1);                // 4
    gemm_mma2<<<dim3(Mrows/128, Gn/128, 2), 256, GB_SMEM>>>(1);                 // 5
    zero_state<<<(Bn * Hn + 255) / 256, 256>>>();                               // 6
    lstm_layer<<<dim3(64, 1, 2), 256, SMEM_BYTES>>>(1, out);                    // 7
}